// round 13
// baseline (speedup 1.0000x reference)
#include <cuda_runtime.h>
#include <cuda_bf16.h>
#include <stdint.h>
#include <math.h>

#define NN 50000
#define EE 800000
#define EQ (EE / 4)
#define HID 128
#define GG 128
#define LAT 32
#define NEG 0.2f
#define XK 64

// ---------------- scratch (static device memory; zero-initialized) ----------------
__device__ float g_h[NN * HID];          // gemm output (fp32)
__device__ float g_y[NN * HID];          // agg output (fp32)
__device__ __nv_bfloat16 g_w0h[128 * 64],  g_w0l[128 * 64];    // W^T [n][k] hi/lo
__device__ __nv_bfloat16 g_w1h[128 * 128], g_w1l[128 * 128];
__device__ __nv_bfloat16 g_w2h[128 * 128], g_w2l[128 * 128];
__device__ float g_as[NN * 4];
__device__ float g_ad[NN * 4];
__device__ int   g_deg[NN];              // invariant: zero before/after each launch
__device__ int   g_rowoff[NN + 1];
__device__ int   g_cur[NN];
__device__ int   g_csr[EE + NN];
__device__ int   g_goff[GG + 1];
__device__ float g_pool[GG * HID];

__device__ __forceinline__ void bsplit(float v, __nv_bfloat16& h, __nv_bfloat16& l) {
    h = __float2bfloat16(v);
    l = __float2bfloat16(v - __bfloat162float(h));
}

// ---------------- prep: split W^T into bf16 hi/lo (tiny) ----------------
__global__ void prepw_kernel(const float* __restrict__ W0, const float* __restrict__ W1,
                             const float* __restrict__ W2)
{
    int i = blockIdx.x * blockDim.x + threadIdx.x;
    if (i < 128 * 64) {
        int n = i / 64, k = i % 64;
        bsplit(W0[k * 128 + n], g_w0h[n * 64 + k], g_w0l[n * 64 + k]);
        return;
    }
    i -= 128 * 64;
    if (i < 128 * 128) {
        int n = i >> 7, k = i & 127;
        bsplit(W1[k * 128 + n], g_w1h[n * 128 + k], g_w1l[n * 128 + k]);
        return;
    }
    i -= 128 * 128;
    if (i < 128 * 128) {
        int n = i >> 7, k = i & 127;
        bsplit(W2[k * 128 + n], g_w2h[n * 128 + k], g_w2l[n * 128 + k]);
    }
}

// ---------------- CSR build (4 edges/thread for atomic MLP) ----------------
__global__ void hist_kernel(const int* __restrict__ dst) {
    int i = blockIdx.x * blockDim.x + threadIdx.x;
    if (i >= EQ) return;
#pragma unroll
    for (int j = 0; j < 4; j++)
        atomicAdd(&g_deg[dst[i + j * EQ]], 1);
}

__global__ void scan_kernel() {
    __shared__ int sums[1024];
    const int T = 1024;
    int t = threadIdx.x;
    const int chunk = (NN + T - 1) / T;
    int start = t * chunk;
    int end = min(start + chunk, NN);
    int s = 0;
    for (int i = start; i < end; i++) s += g_deg[i] + 1;
    sums[t] = s;
    __syncthreads();
    for (int off = 1; off < T; off <<= 1) {
        int v = 0;
        if (t >= off) v = sums[t - off];
        __syncthreads();
        if (t >= off) sums[t] += v;
        __syncthreads();
    }
    int base = (t == 0) ? 0 : sums[t - 1];
    for (int i = start; i < end; i++) {
        g_rowoff[i] = base;
        g_cur[i] = base;
        base += g_deg[i] + 1;
        g_deg[i] = 0;
    }
    if (t == 0) g_rowoff[NN] = sums[T - 1];
}

__global__ void scatter_kernel(const int* __restrict__ src, const int* __restrict__ dst) {
    int i = blockIdx.x * blockDim.x + threadIdx.x;
    if (i < EQ) {
#pragma unroll
        for (int j = 0; j < 4; j++) {
            int e = i + j * EQ;
            int d = dst[e];
            int pos = atomicAdd(&g_cur[d], 1);
            g_csr[pos] = src[e];
        }
    } else if (i < EQ + NN) {
        int n = i - EQ;
        int pos = atomicAdd(&g_cur[n], 1);
        g_csr[pos] = n;
    }
}

__global__ void gbound_kernel(const int* __restrict__ batch) {
    int i = blockIdx.x * blockDim.x + threadIdx.x;
    if (i >= NN) return;
    int b = batch[i];
    int prev = (i == 0) ? -1 : batch[i - 1];
    for (int g = prev + 1; g <= b; g++) g_goff[g] = i;
    if (i == NN - 1) {
        for (int g = b + 1; g <= GG; g++) g_goff[g] = NN;
    }
}

// ---------------- HMMA bf16 split GEMM + fused alpha ----------------------------
#define ASTR 40

#define MMA16816(d, a, b0v, b1v) \
    asm volatile("mma.sync.aligned.m16n8k16.row.col.f32.bf16.bf16.f32 " \
        "{%0,%1,%2,%3}, {%4,%5,%6,%7}, {%8,%9}, {%0,%1,%2,%3};" \
        : "+f"((d)[0]), "+f"((d)[1]), "+f"((d)[2]), "+f"((d)[3]) \
        : "r"((a)[0]), "r"((a)[1]), "r"((a)[2]), "r"((a)[3]), "r"(b0v), "r"(b1v))

__device__ __forceinline__ uint32_t pack_bf2(__nv_bfloat16 lo, __nv_bfloat16 hi) {
    return ((uint32_t)__bfloat16_as_ushort(hi) << 16) | __bfloat16_as_ushort(lo);
}

__global__ __launch_bounds__(256, 2) void gemm_kernel(
    const float* __restrict__ X,
    const __nv_bfloat16* __restrict__ Bh, const __nv_bfloat16* __restrict__ Bl,
    float* __restrict__ Out, int nrows, int K,
    const float* __restrict__ a_src, const float* __restrict__ a_dst)
{
    __shared__ __align__(16) __nv_bfloat16 Ah_s[128 * ASTR];
    __shared__ __align__(16) __nv_bfloat16 Al_s[128 * ASTR];
    __shared__ __align__(16) __nv_bfloat16 Bh_s[128 * ASTR];
    __shared__ __align__(16) __nv_bfloat16 Bl_s[128 * ASTR];
    __shared__ float spart[128][4][2];
    __shared__ float sAs[128], sAd[128];

    int tid = threadIdx.x;
    int wid = tid >> 5, lane = tid & 31;
    int g = lane >> 2, tg = lane & 3;
    int rbase = (wid >> 1) * 32;
    int cbase = (wid & 1) * 64;
    int row0 = blockIdx.x * 128;

    if (tid < 128) { sAs[tid] = a_src[tid]; sAd[tid] = a_dst[tid]; }

    float acc[2][8][4];
#pragma unroll
    for (int mt = 0; mt < 2; mt++)
#pragma unroll
        for (int nt = 0; nt < 8; nt++)
#pragma unroll
            for (int q = 0; q < 4; q++) acc[mt][nt][q] = 0.f;

    int lrow = tid >> 1, lhalf = tid & 1;
    int grow = row0 + lrow;
    bool valid = grow < nrows;
    int k0 = lhalf * 16;

    const int NCH = K >> 5;
    for (int ch = 0; ch < NCH; ch++) {
        {
            const float4* xsrc = (const float4*)(X + (size_t)grow * K + ch * 32 + k0);
            uint32_t* dh = (uint32_t*)&Ah_s[lrow * ASTR + k0];
            uint32_t* dl = (uint32_t*)&Al_s[lrow * ASTR + k0];
#pragma unroll
            for (int j = 0; j < 4; j++) {
                float4 v = make_float4(0.f, 0.f, 0.f, 0.f);
                if (valid) v = __ldg(xsrc + j);
                __nv_bfloat16 h0, h1, h2, h3, l0, l1, l2, l3;
                bsplit(v.x, h0, l0); bsplit(v.y, h1, l1);
                bsplit(v.z, h2, l2); bsplit(v.w, h3, l3);
                dh[j * 2]     = pack_bf2(h0, h1);
                dh[j * 2 + 1] = pack_bf2(h2, h3);
                dl[j * 2]     = pack_bf2(l0, l1);
                dl[j * 2 + 1] = pack_bf2(l2, l3);
            }
        }
        {
            const uint4* ph = (const uint4*)(Bh + (size_t)lrow * K + ch * 32 + k0);
            const uint4* pl = (const uint4*)(Bl + (size_t)lrow * K + ch * 32 + k0);
            uint4 vh0 = __ldg(ph), vh1 = __ldg(ph + 1);
            uint4 vl0 = __ldg(pl), vl1 = __ldg(pl + 1);
            uint4* dh = (uint4*)&Bh_s[lrow * ASTR + k0];
            uint4* dl = (uint4*)&Bl_s[lrow * ASTR + k0];
            dh[0] = vh0; dh[1] = vh1;
            dl[0] = vl0; dl[1] = vl1;
        }
        __syncthreads();

#pragma unroll
        for (int ks = 0; ks < 2; ks++) {
            int kb = ks * 16;
            uint32_t ah[2][4], al[2][4];
#pragma unroll
            for (int mt = 0; mt < 2; mt++) {
                int r = rbase + mt * 16 + g;
                const __nv_bfloat16* ap = &Ah_s[r * ASTR + kb + tg * 2];
                ah[mt][0] = *(const uint32_t*)ap;
                ah[mt][1] = *(const uint32_t*)(ap + 8 * ASTR);
                ah[mt][2] = *(const uint32_t*)(ap + 8);
                ah[mt][3] = *(const uint32_t*)(ap + 8 * ASTR + 8);
                const __nv_bfloat16* lp = &Al_s[r * ASTR + kb + tg * 2];
                al[mt][0] = *(const uint32_t*)lp;
                al[mt][1] = *(const uint32_t*)(lp + 8 * ASTR);
                al[mt][2] = *(const uint32_t*)(lp + 8);
                al[mt][3] = *(const uint32_t*)(lp + 8 * ASTR + 8);
            }
#pragma unroll
            for (int nt = 0; nt < 8; nt++) {
                int nb = cbase + nt * 8 + g;
                const __nv_bfloat16* bp = &Bh_s[nb * ASTR + kb + tg * 2];
                uint32_t bh0 = *(const uint32_t*)bp;
                uint32_t bh1 = *(const uint32_t*)(bp + 8);
                const __nv_bfloat16* qp = &Bl_s[nb * ASTR + kb + tg * 2];
                uint32_t bl0 = *(const uint32_t*)qp;
                uint32_t bl1 = *(const uint32_t*)(qp + 8);
#pragma unroll
                for (int mt = 0; mt < 2; mt++) {
                    MMA16816(acc[mt][nt], ah[mt], bh0, bh1);
                    MMA16816(acc[mt][nt], al[mt], bh0, bh1);
                    MMA16816(acc[mt][nt], ah[mt], bl0, bl1);
                }
            }
        }
        __syncthreads();
    }

    // ---- fused alpha partials ----
    {
        float pA[2][2][2], pD[2][2][2];
#pragma unroll
        for (int mt = 0; mt < 2; mt++)
#pragma unroll
            for (int sb = 0; sb < 2; sb++)
#pragma unroll
                for (int hh = 0; hh < 2; hh++) { pA[mt][sb][hh] = 0.f; pD[mt][sb][hh] = 0.f; }
#pragma unroll
        for (int mt = 0; mt < 2; mt++)
#pragma unroll
            for (int nt = 0; nt < 8; nt++) {
                int hh = nt >> 2;
                int c0 = cbase + nt * 8 + tg * 2;
                float a0 = sAs[c0], a1 = sAs[c0 + 1];
                float d0 = sAd[c0], d1 = sAd[c0 + 1];
                pA[mt][0][hh] += acc[mt][nt][0] * a0 + acc[mt][nt][1] * a1;
                pA[mt][1][hh] += acc[mt][nt][2] * a0 + acc[mt][nt][3] * a1;
                pD[mt][0][hh] += acc[mt][nt][0] * d0 + acc[mt][nt][1] * d1;
                pD[mt][1][hh] += acc[mt][nt][2] * d0 + acc[mt][nt][3] * d1;
            }
#pragma unroll
        for (int mt = 0; mt < 2; mt++)
#pragma unroll
            for (int sb = 0; sb < 2; sb++)
#pragma unroll
                for (int hh = 0; hh < 2; hh++) {
                    float vA = pA[mt][sb][hh], vD = pD[mt][sb][hh];
                    vA += __shfl_xor_sync(0xffffffffu, vA, 1);
                    vA += __shfl_xor_sync(0xffffffffu, vA, 2);
                    vD += __shfl_xor_sync(0xffffffffu, vD, 1);
                    vD += __shfl_xor_sync(0xffffffffu, vD, 2);
                    if (tg == 0) {
                        int row = rbase + mt * 16 + sb * 8 + g;
                        int head = (wid & 1) * 2 + hh;
                        spart[row][head][0] = vA;
                        spart[row][head][1] = vD;
                    }
                }
    }

#pragma unroll
    for (int mt = 0; mt < 2; mt++) {
        int r1 = row0 + rbase + mt * 16 + g;
        int r2 = r1 + 8;
#pragma unroll
        for (int nt = 0; nt < 8; nt++) {
            int c = cbase + nt * 8 + tg * 2;
            if (r1 < nrows)
                *(float2*)&Out[(size_t)r1 * 128 + c] = make_float2(acc[mt][nt][0], acc[mt][nt][1]);
            if (r2 < nrows)
                *(float2*)&Out[(size_t)r2 * 128 + c] = make_float2(acc[mt][nt][2], acc[mt][nt][3]);
        }
    }

    __syncthreads();
    if (tid < 128) {
        int gr = row0 + tid;
        if (gr < nrows) {
            *(float4*)&g_as[gr * 4] = make_float4(spart[tid][0][0], spart[tid][1][0],
                                                  spart[tid][2][0], spart[tid][3][0]);
            *(float4*)&g_ad[gr * 4] = make_float4(spart[tid][0][1], spart[tid][1][1],
                                                  spart[tid][2][1], spart[tid][3][1]);
        }
    }
}

// ---------------- aggregation: 2 warps per node, edges split (no redundant gather)
// Block = 256 threads = 8 warps = 4 nodes. Warp pr owns its half of the edge list.
// Combine max / denom / acc via smem + 2 block barriers.
__global__ __launch_bounds__(256) void agg_kernel(
    const float* __restrict__ hbuf, const float* __restrict__ bias,
    float* __restrict__ outbuf)
{
    __shared__ int    s_src[8][32];
    __shared__ float4 s_p[8][32];
    __shared__ float4 s_mx[4][2];
    __shared__ float4 s_sum[4][2];
    __shared__ float4 s_acc[4][32];

    int wi = threadIdx.x >> 5;
    int nl = wi >> 1, pr = wi & 1;
    int n = blockIdx.x * 4 + nl;        // NN = 50000 = 4*12500, exact
    int lane = threadIdx.x & 31;
    int head = lane >> 3;
    int col = head * 32 + (lane & 7) * 4;

    float4 adv = *(const float4*)&g_ad[n * 4];
    int beg = g_rowoff[n], end = g_rowoff[n + 1];
    int cnt = end - beg;
    int half = (cnt + 1) >> 1;
    int b0 = pr ? (beg + half) : beg;
    int e0 = pr ? end : (beg + half);
    int ci = e0 - b0;
    bool fast = (ci <= 32);

    // ---- phase A: partial max over my edges ----
    int s = 0;
    float4 ev = make_float4(-1e30f, -1e30f, -1e30f, -1e30f);
    float4 mxp = ev;
    if (fast) {
        if (lane < ci) {
            s = __ldg(&g_csr[b0 + lane]);
            float4 a = __ldg((const float4*)&g_as[s * 4]);
            float e;
            e = a.x + adv.x; ev.x = fmaxf(e, NEG * e);
            e = a.y + adv.y; ev.y = fmaxf(e, NEG * e);
            e = a.z + adv.z; ev.z = fmaxf(e, NEG * e);
            e = a.w + adv.w; ev.w = fmaxf(e, NEG * e);
        }
        mxp = ev;
    } else {
        for (int p = b0 + lane; p < e0; p += 32) {
            int sp = __ldg(&g_csr[p]);
            float4 a = __ldg((const float4*)&g_as[sp * 4]);
            float e;
            e = a.x + adv.x; mxp.x = fmaxf(mxp.x, fmaxf(e, NEG * e));
            e = a.y + adv.y; mxp.y = fmaxf(mxp.y, fmaxf(e, NEG * e));
            e = a.z + adv.z; mxp.z = fmaxf(mxp.z, fmaxf(e, NEG * e));
            e = a.w + adv.w; mxp.w = fmaxf(mxp.w, fmaxf(e, NEG * e));
        }
    }
#pragma unroll
    for (int off = 16; off; off >>= 1) {
        mxp.x = fmaxf(mxp.x, __shfl_xor_sync(0xffffffffu, mxp.x, off));
        mxp.y = fmaxf(mxp.y, __shfl_xor_sync(0xffffffffu, mxp.y, off));
        mxp.z = fmaxf(mxp.z, __shfl_xor_sync(0xffffffffu, mxp.z, off));
        mxp.w = fmaxf(mxp.w, __shfl_xor_sync(0xffffffffu, mxp.w, off));
    }
    if (lane == 0) s_mx[nl][pr] = mxp;
    __syncthreads();
    float4 m0 = s_mx[nl][0], m1 = s_mx[nl][1];
    float4 mx = make_float4(fmaxf(m0.x, m1.x), fmaxf(m0.y, m1.y),
                            fmaxf(m0.z, m1.z), fmaxf(m0.w, m1.w));

    // ---- phase B: softmax weights + gather-accumulate over my edges ----
    float4 acc = make_float4(0.f, 0.f, 0.f, 0.f);
    float4 ss  = acc;
    if (fast) {
        float4 pv = make_float4(0.f, 0.f, 0.f, 0.f);
        if (lane < ci) {
            pv.x = __expf(ev.x - mx.x);
            pv.y = __expf(ev.y - mx.y);
            pv.z = __expf(ev.z - mx.z);
            pv.w = __expf(ev.w - mx.w);
            ss = pv;
        }
        s_src[wi][lane] = s;
        s_p[wi][lane] = pv;
        __syncwarp();
        for (int j = 0; j < ci; j++) {
            int sj = s_src[wi][j];
            float pj = ((const float*)&s_p[wi][j])[head];
            float4 hv = __ldg((const float4*)(hbuf + sj * 128 + col));
            acc.x = fmaf(pj, hv.x, acc.x);
            acc.y = fmaf(pj, hv.y, acc.y);
            acc.z = fmaf(pj, hv.z, acc.z);
            acc.w = fmaf(pj, hv.w, acc.w);
        }
        __syncwarp();
    } else {
        for (int c0 = b0; c0 < e0; c0 += 32) {
            int cc = min(32, e0 - c0);
            float4 pv = make_float4(0.f, 0.f, 0.f, 0.f);
            int sp = 0;
            if (lane < cc) {
                sp = __ldg(&g_csr[c0 + lane]);
                float4 a = __ldg((const float4*)&g_as[sp * 4]);
                float e;
                e = a.x + adv.x; e = fmaxf(e, NEG * e); pv.x = __expf(e - mx.x);
                e = a.y + adv.y; e = fmaxf(e, NEG * e); pv.y = __expf(e - mx.y);
                e = a.z + adv.z; e = fmaxf(e, NEG * e); pv.z = __expf(e - mx.z);
                e = a.w + adv.w; e = fmaxf(e, NEG * e); pv.w = __expf(e - mx.w);
                ss.x += pv.x; ss.y += pv.y; ss.z += pv.z; ss.w += pv.w;
            }
            s_src[wi][lane] = sp;
            s_p[wi][lane] = pv;
            __syncwarp();
            for (int j = 0; j < cc; j++) {
                int sj = s_src[wi][j];
                float pj = ((const float*)&s_p[wi][j])[head];
                float4 hv = __ldg((const float4*)(hbuf + sj * 128 + col));
                acc.x = fmaf(pj, hv.x, acc.x);
                acc.y = fmaf(pj, hv.y, acc.y);
                acc.z = fmaf(pj, hv.z, acc.z);
                acc.w = fmaf(pj, hv.w, acc.w);
            }
            __syncwarp();
        }
    }

    // warp-reduce my denominator
#pragma unroll
    for (int off = 16; off; off >>= 1) {
        ss.x += __shfl_xor_sync(0xffffffffu, ss.x, off);
        ss.y += __shfl_xor_sync(0xffffffffu, ss.y, off);
        ss.z += __shfl_xor_sync(0xffffffffu, ss.z, off);
        ss.w += __shfl_xor_sync(0xffffffffu, ss.w, off);
    }
    if (lane == 0) s_sum[nl][pr] = ss;
    if (pr) s_acc[nl][lane] = acc;
    __syncthreads();

    if (!pr) {
        float4 oa = s_acc[nl][lane];
        acc.x += oa.x; acc.y += oa.y; acc.z += oa.z; acc.w += oa.w;
        float4 os = s_sum[nl][1];
        float4 st = make_float4(ss.x + os.x, ss.y + os.y, ss.z + os.z, ss.w + os.w);
        float sh = (head == 0) ? st.x : (head == 1) ? st.y : (head == 2) ? st.z : st.w;
        float inv = 1.0f / (sh + 1e-16f);

        float4 b = *(const float4*)(bias + col);
        float4 o;
        o.x = acc.x * inv + b.x; o.x = fmaxf(o.x, NEG * o.x);
        o.y = acc.y * inv + b.y; o.y = fmaxf(o.y, NEG * o.y);
        o.z = acc.z * inv + b.z; o.z = fmaxf(o.z, NEG * o.z);
        o.w = acc.w * inv + b.w; o.w = fmaxf(o.w, NEG * o.w);
        *(float4*)(outbuf + (size_t)n * 128 + col) = o;
    }
}

// ---------------- pooling: segmented over sorted batch ----------------
__global__ __launch_bounds__(512) void pool_kernel(const float* __restrict__ y) {
    __shared__ float sh[3][128];
    int g = blockIdx.x;
    int s = g_goff[g], e = g_goff[g + 1];
    int c = threadIdx.x & 127;
    int r = threadIdx.x >> 7;
    float acc = 0.f;
    for (int i = s + r; i < e; i += 4) acc += y[(size_t)i * 128 + c];
    if (r) sh[r - 1][c] = acc;
    __syncthreads();
    if (!r) g_pool[g * 128 + c] = ((acc + sh[0][c]) + (sh[1][c] + sh[2][c]));
}

// ---------------- head ----------------
__global__ void head_kernel(const float* __restrict__ fc_w, const float* __restrict__ fc_b,
                            const float* __restrict__ bn_g, const float* __restrict__ bn_b,
                            float* __restrict__ out)
{
    int g = blockIdx.x;
    int l = threadIdx.x;
    const float* pr = g_pool + g * HID;
    float s = 0.f;
#pragma unroll 8
    for (int k = 0; k < HID; k++) s = fmaf(pr[k], fc_w[k * LAT + l], s);
    s += fc_b[l];
    const float inv = 0.999995000037499688f;  // 1/sqrt(1 + 1e-5)
    out[g * LAT + l] = bn_g[l] * s * inv + bn_b[l];
}

// ---------------- launch ----------------
extern "C" void kernel_launch(void* const* d_in, const int* in_sizes, int n_in,
                              void* d_out, int out_size)
{
    const float* x       = (const float*)d_in[0];
    const int*   eidx    = (const int*)  d_in[1];
    const int*   batch   = (const int*)  d_in[2];
    const float* W0      = (const float*)d_in[3];
    const float* a_src0  = (const float*)d_in[4];
    const float* a_dst0  = (const float*)d_in[5];
    const float* b0      = (const float*)d_in[6];
    const float* W1      = (const float*)d_in[7];
    const float* a_src1  = (const float*)d_in[8];
    const float* a_dst1  = (const float*)d_in[9];
    const float* b1      = (const float*)d_in[10];
    const float* W2      = (const float*)d_in[11];
    const float* a_src2  = (const float*)d_in[12];
    const float* a_dst2  = (const float*)d_in[13];
    const float* b2      = (const float*)d_in[14];
    const float* fc_w    = (const float*)d_in[15];
    const float* fc_b    = (const float*)d_in[16];
    const float* bn_g    = (const float*)d_in[17];
    const float* bn_b    = (const float*)d_in[18];
    float* out = (float*)d_out;

    const int* src = eidx;
    const int* dst = eidx + EE;

    float *ph, *py;
    __nv_bfloat16 *pw0h, *pw0l, *pw1h, *pw1l, *pw2h, *pw2l;
    cudaGetSymbolAddress((void**)&ph, g_h);
    cudaGetSymbolAddress((void**)&py, g_y);
    cudaGetSymbolAddress((void**)&pw0h, g_w0h);
    cudaGetSymbolAddress((void**)&pw0l, g_w0l);
    cudaGetSymbolAddress((void**)&pw1h, g_w1h);
    cudaGetSymbolAddress((void**)&pw1l, g_w1l);
    cudaGetSymbolAddress((void**)&pw2h, g_w2h);
    cudaGetSymbolAddress((void**)&pw2l, g_w2l);

    const int PREPW_TOT = 128 * 64 + 2 * 128 * 128;
    const int gemm_grid = (NN + 127) / 128;
    const int agg_grid  = NN / 4;    // 4 nodes per 256-thread block (2 warps/node)

    prepw_kernel<<<(PREPW_TOT + 255) / 256, 256>>>(W0, W1, W2);
    hist_kernel<<<(EQ + 255) / 256, 256>>>(dst);
    scan_kernel<<<1, 1024>>>();
    scatter_kernel<<<(EQ + NN + 255) / 256, 256>>>(src, dst);
    gemm_kernel<<<gemm_grid, 256>>>(x, pw0h, pw0l, ph, NN, XK, a_src0, a_dst0);
    agg_kernel<<<agg_grid, 256>>>(ph, b0, py);

    gemm_kernel<<<gemm_grid, 256>>>(py, pw1h, pw1l, ph, NN, HID, a_src1, a_dst1);
    agg_kernel<<<agg_grid, 256>>>(ph, b1, py);

    gemm_kernel<<<gemm_grid, 256>>>(py, pw2h, pw2l, ph, NN, HID, a_src2, a_dst2);
    agg_kernel<<<agg_grid, 256>>>(ph, b2, py);

    gbound_kernel<<<(NN + 255) / 256, 256>>>(batch);
    pool_kernel<<<GG, 512>>>(py);
    head_kernel<<<GG, LAT>>>(fc_w, fc_b, bn_g, bn_b, out);
}

// round 14
// speedup vs baseline: 1.6414x; 1.6414x over previous
#include <cuda_runtime.h>
#include <cuda_bf16.h>
#include <stdint.h>
#include <math.h>

#define NN 50000
#define EE 800000
#define HID 128
#define GG 128
#define LAT 32
#define NEG 0.2f
#define XK 64
#define SCB 196   // ceil(NN/256) scan blocks

// ---------------- scratch (static device memory; zero-initialized) ----------------
__device__ float g_h[NN * HID];          // gemm output (fp32)
__device__ float g_y[NN * HID];          // agg output (fp32)
__device__ __nv_bfloat16 g_w0h[128 * 64],  g_w0l[128 * 64];    // W^T [n][k] hi/lo
__device__ __nv_bfloat16 g_w1h[128 * 128], g_w1l[128 * 128];
__device__ __nv_bfloat16 g_w2h[128 * 128], g_w2l[128 * 128];
__device__ float g_as[NN * 4];
__device__ float g_ad[NN * 4];
__device__ int   g_deg[NN];              // invariant: zero before/after each launch
__device__ int   g_rowoff[NN + 1];
__device__ int   g_cur[NN];
__device__ int   g_csr[EE + NN];
__device__ int   g_goff[GG + 1];
__device__ int   g_bsum[SCB];
__device__ int   g_boff[SCB];
__device__ float g_pool[GG * HID];

__device__ __forceinline__ void bsplit(float v, __nv_bfloat16& h, __nv_bfloat16& l) {
    h = __float2bfloat16(v);
    l = __float2bfloat16(v - __bfloat162float(h));
}

// ---------------- prep: split W^T into bf16 hi/lo (tiny) ----------------
__global__ void prepw_kernel(const float* __restrict__ W0, const float* __restrict__ W1,
                             const float* __restrict__ W2)
{
    int i = blockIdx.x * blockDim.x + threadIdx.x;
    if (i < 128 * 64) {
        int n = i / 64, k = i % 64;
        bsplit(W0[k * 128 + n], g_w0h[n * 64 + k], g_w0l[n * 64 + k]);
        return;
    }
    i -= 128 * 64;
    if (i < 128 * 128) {
        int n = i >> 7, k = i & 127;
        bsplit(W1[k * 128 + n], g_w1h[n * 128 + k], g_w1l[n * 128 + k]);
        return;
    }
    i -= 128 * 128;
    if (i < 128 * 128) {
        int n = i >> 7, k = i & 127;
        bsplit(W2[k * 128 + n], g_w2h[n * 128 + k], g_w2l[n * 128 + k]);
    }
}

// ---------------- CSR build ----------------
__global__ void hist_kernel(const int* __restrict__ dst) {
    int i = blockIdx.x * blockDim.x + threadIdx.x;
    if (i < EE) atomicAdd(&g_deg[dst[i]], 1);
}

// 3-phase scan of (deg+1)
__global__ void scan1_kernel() {   // per-block sums
    __shared__ int red[256];
    int i = blockIdx.x * 256 + threadIdx.x;
    int v = (i < NN) ? (g_deg[i] + 1) : 0;
    red[threadIdx.x] = v;
    __syncthreads();
#pragma unroll
    for (int off = 128; off; off >>= 1) {
        if (threadIdx.x < off) red[threadIdx.x] += red[threadIdx.x + off];
        __syncthreads();
    }
    if (threadIdx.x == 0) g_bsum[blockIdx.x] = red[0];
}

__global__ void scan2_kernel() {   // exclusive prefix of SCB partials (1 block)
    __shared__ int sc[256];
    int t = threadIdx.x;
    sc[t] = (t < SCB) ? g_bsum[t] : 0;
    __syncthreads();
    for (int off = 1; off < 256; off <<= 1) {
        int v = (t >= off) ? sc[t - off] : 0;
        __syncthreads();
        sc[t] += v;
        __syncthreads();
    }
    if (t < SCB) g_boff[t] = sc[t] - g_bsum[t];   // exclusive
}

__global__ void scan3_kernel() {   // apply offsets, write rowoff/cur, zero deg
    __shared__ int sc[256];
    int t = threadIdx.x;
    int i = blockIdx.x * 256 + t;
    int v = (i < NN) ? (g_deg[i] + 1) : 0;
    sc[t] = v;
    __syncthreads();
    for (int off = 1; off < 256; off <<= 1) {
        int u = (t >= off) ? sc[t - off] : 0;
        __syncthreads();
        sc[t] += u;
        __syncthreads();
    }
    int excl = sc[t] - v + g_boff[blockIdx.x];
    if (i < NN) {
        g_rowoff[i] = excl;
        g_cur[i] = excl;
        g_deg[i] = 0;
        if (i == NN - 1) g_rowoff[NN] = excl + v;
    }
}

__global__ void scatter_kernel(const int* __restrict__ src, const int* __restrict__ dst) {
    int i = blockIdx.x * blockDim.x + threadIdx.x;
    if (i < EE) {
        int d = dst[i];
        int pos = atomicAdd(&g_cur[d], 1);
        g_csr[pos] = src[i];
    } else if (i < EE + NN) {
        int n = i - EE;
        int pos = atomicAdd(&g_cur[n], 1);
        g_csr[pos] = n;
    }
}

__global__ void gbound_kernel(const int* __restrict__ batch) {
    int i = blockIdx.x * blockDim.x + threadIdx.x;
    if (i >= NN) return;
    int b = batch[i];
    int prev = (i == 0) ? -1 : batch[i - 1];
    for (int g = prev + 1; g <= b; g++) g_goff[g] = i;
    if (i == NN - 1) {
        for (int g = b + 1; g <= GG; g++) g_goff[g] = NN;
    }
}

// ---------------- HMMA bf16 split GEMM + fused alpha ----------------------------
#define ASTR 40

#define MMA16816(d, a, b0v, b1v) \
    asm volatile("mma.sync.aligned.m16n8k16.row.col.f32.bf16.bf16.f32 " \
        "{%0,%1,%2,%3}, {%4,%5,%6,%7}, {%8,%9}, {%0,%1,%2,%3};" \
        : "+f"((d)[0]), "+f"((d)[1]), "+f"((d)[2]), "+f"((d)[3]) \
        : "r"((a)[0]), "r"((a)[1]), "r"((a)[2]), "r"((a)[3]), "r"(b0v), "r"(b1v))

__device__ __forceinline__ uint32_t pack_bf2(__nv_bfloat16 lo, __nv_bfloat16 hi) {
    return ((uint32_t)__bfloat16_as_ushort(hi) << 16) | __bfloat16_as_ushort(lo);
}

__global__ __launch_bounds__(256, 2) void gemm_kernel(
    const float* __restrict__ X,
    const __nv_bfloat16* __restrict__ Bh, const __nv_bfloat16* __restrict__ Bl,
    float* __restrict__ Out, int nrows, int K,
    const float* __restrict__ a_src, const float* __restrict__ a_dst)
{
    __shared__ __align__(16) __nv_bfloat16 Ah_s[128 * ASTR];
    __shared__ __align__(16) __nv_bfloat16 Al_s[128 * ASTR];
    __shared__ __align__(16) __nv_bfloat16 Bh_s[128 * ASTR];
    __shared__ __align__(16) __nv_bfloat16 Bl_s[128 * ASTR];
    __shared__ float spart[128][4][2];
    __shared__ float sAs[128], sAd[128];

    int tid = threadIdx.x;
    int wid = tid >> 5, lane = tid & 31;
    int g = lane >> 2, tg = lane & 3;
    int rbase = (wid >> 1) * 32;
    int cbase = (wid & 1) * 64;
    int row0 = blockIdx.x * 128;

    if (tid < 128) { sAs[tid] = a_src[tid]; sAd[tid] = a_dst[tid]; }

    float acc[2][8][4];
#pragma unroll
    for (int mt = 0; mt < 2; mt++)
#pragma unroll
        for (int nt = 0; nt < 8; nt++)
#pragma unroll
            for (int q = 0; q < 4; q++) acc[mt][nt][q] = 0.f;

    int lrow = tid >> 1, lhalf = tid & 1;
    int grow = row0 + lrow;
    bool valid = grow < nrows;
    int k0 = lhalf * 16;

    const int NCH = K >> 5;
    for (int ch = 0; ch < NCH; ch++) {
        {
            const float4* xsrc = (const float4*)(X + (size_t)grow * K + ch * 32 + k0);
            uint32_t* dh = (uint32_t*)&Ah_s[lrow * ASTR + k0];
            uint32_t* dl = (uint32_t*)&Al_s[lrow * ASTR + k0];
#pragma unroll
            for (int j = 0; j < 4; j++) {
                float4 v = make_float4(0.f, 0.f, 0.f, 0.f);
                if (valid) v = __ldg(xsrc + j);
                __nv_bfloat16 h0, h1, h2, h3, l0, l1, l2, l3;
                bsplit(v.x, h0, l0); bsplit(v.y, h1, l1);
                bsplit(v.z, h2, l2); bsplit(v.w, h3, l3);
                dh[j * 2]     = pack_bf2(h0, h1);
                dh[j * 2 + 1] = pack_bf2(h2, h3);
                dl[j * 2]     = pack_bf2(l0, l1);
                dl[j * 2 + 1] = pack_bf2(l2, l3);
            }
        }
        {
            const uint4* ph = (const uint4*)(Bh + (size_t)lrow * K + ch * 32 + k0);
            const uint4* pl = (const uint4*)(Bl + (size_t)lrow * K + ch * 32 + k0);
            uint4 vh0 = __ldg(ph), vh1 = __ldg(ph + 1);
            uint4 vl0 = __ldg(pl), vl1 = __ldg(pl + 1);
            uint4* dh = (uint4*)&Bh_s[lrow * ASTR + k0];
            uint4* dl = (uint4*)&Bl_s[lrow * ASTR + k0];
            dh[0] = vh0; dh[1] = vh1;
            dl[0] = vl0; dl[1] = vl1;
        }
        __syncthreads();

#pragma unroll
        for (int ks = 0; ks < 2; ks++) {
            int kb = ks * 16;
            uint32_t ah[2][4], al[2][4];
#pragma unroll
            for (int mt = 0; mt < 2; mt++) {
                int r = rbase + mt * 16 + g;
                const __nv_bfloat16* ap = &Ah_s[r * ASTR + kb + tg * 2];
                ah[mt][0] = *(const uint32_t*)ap;
                ah[mt][1] = *(const uint32_t*)(ap + 8 * ASTR);
                ah[mt][2] = *(const uint32_t*)(ap + 8);
                ah[mt][3] = *(const uint32_t*)(ap + 8 * ASTR + 8);
                const __nv_bfloat16* lp = &Al_s[r * ASTR + kb + tg * 2];
                al[mt][0] = *(const uint32_t*)lp;
                al[mt][1] = *(const uint32_t*)(lp + 8 * ASTR);
                al[mt][2] = *(const uint32_t*)(lp + 8);
                al[mt][3] = *(const uint32_t*)(lp + 8 * ASTR + 8);
            }
#pragma unroll
            for (int nt = 0; nt < 8; nt++) {
                int nb = cbase + nt * 8 + g;
                const __nv_bfloat16* bp = &Bh_s[nb * ASTR + kb + tg * 2];
                uint32_t bh0 = *(const uint32_t*)bp;
                uint32_t bh1 = *(const uint32_t*)(bp + 8);
                const __nv_bfloat16* qp = &Bl_s[nb * ASTR + kb + tg * 2];
                uint32_t bl0 = *(const uint32_t*)qp;
                uint32_t bl1 = *(const uint32_t*)(qp + 8);
#pragma unroll
                for (int mt = 0; mt < 2; mt++) {
                    MMA16816(acc[mt][nt], ah[mt], bh0, bh1);
                    MMA16816(acc[mt][nt], al[mt], bh0, bh1);
                    MMA16816(acc[mt][nt], ah[mt], bl0, bl1);
                }
            }
        }
        __syncthreads();
    }

    // ---- fused alpha partials ----
    {
        float pA[2][2][2], pD[2][2][2];
#pragma unroll
        for (int mt = 0; mt < 2; mt++)
#pragma unroll
            for (int sb = 0; sb < 2; sb++)
#pragma unroll
                for (int hh = 0; hh < 2; hh++) { pA[mt][sb][hh] = 0.f; pD[mt][sb][hh] = 0.f; }
#pragma unroll
        for (int mt = 0; mt < 2; mt++)
#pragma unroll
            for (int nt = 0; nt < 8; nt++) {
                int hh = nt >> 2;
                int c0 = cbase + nt * 8 + tg * 2;
                float a0 = sAs[c0], a1 = sAs[c0 + 1];
                float d0 = sAd[c0], d1 = sAd[c0 + 1];
                pA[mt][0][hh] += acc[mt][nt][0] * a0 + acc[mt][nt][1] * a1;
                pA[mt][1][hh] += acc[mt][nt][2] * a0 + acc[mt][nt][3] * a1;
                pD[mt][0][hh] += acc[mt][nt][0] * d0 + acc[mt][nt][1] * d1;
                pD[mt][1][hh] += acc[mt][nt][2] * d0 + acc[mt][nt][3] * d1;
            }
#pragma unroll
        for (int mt = 0; mt < 2; mt++)
#pragma unroll
            for (int sb = 0; sb < 2; sb++)
#pragma unroll
                for (int hh = 0; hh < 2; hh++) {
                    float vA = pA[mt][sb][hh], vD = pD[mt][sb][hh];
                    vA += __shfl_xor_sync(0xffffffffu, vA, 1);
                    vA += __shfl_xor_sync(0xffffffffu, vA, 2);
                    vD += __shfl_xor_sync(0xffffffffu, vD, 1);
                    vD += __shfl_xor_sync(0xffffffffu, vD, 2);
                    if (tg == 0) {
                        int row = rbase + mt * 16 + sb * 8 + g;
                        int head = (wid & 1) * 2 + hh;
                        spart[row][head][0] = vA;
                        spart[row][head][1] = vD;
                    }
                }
    }

#pragma unroll
    for (int mt = 0; mt < 2; mt++) {
        int r1 = row0 + rbase + mt * 16 + g;
        int r2 = r1 + 8;
#pragma unroll
        for (int nt = 0; nt < 8; nt++) {
            int c = cbase + nt * 8 + tg * 2;
            if (r1 < nrows)
                *(float2*)&Out[(size_t)r1 * 128 + c] = make_float2(acc[mt][nt][0], acc[mt][nt][1]);
            if (r2 < nrows)
                *(float2*)&Out[(size_t)r2 * 128 + c] = make_float2(acc[mt][nt][2], acc[mt][nt][3]);
        }
    }

    __syncthreads();
    if (tid < 128) {
        int gr = row0 + tid;
        if (gr < nrows) {
            *(float4*)&g_as[gr * 4] = make_float4(spart[tid][0][0], spart[tid][1][0],
                                                  spart[tid][2][0], spart[tid][3][0]);
            *(float4*)&g_ad[gr * 4] = make_float4(spart[tid][0][1], spart[tid][1][1],
                                                  spart[tid][2][1], spart[tid][3][1]);
        }
    }
}

// ---------------- aggregation: one warp per dst node; deg<=32 single-pass -------
__global__ __launch_bounds__(256) void agg_kernel(
    const float* __restrict__ hbuf, const float* __restrict__ bias,
    float* __restrict__ outbuf)
{
    __shared__ int    s_src[8][32];
    __shared__ float4 s_p[8][32];

    int wi = threadIdx.x >> 5;
    int n = (blockIdx.x * blockDim.x + threadIdx.x) >> 5;
    if (n >= NN) return;
    int lane = threadIdx.x & 31;
    int head = lane >> 3;
    int col = head * 32 + (lane & 7) * 4;

    float4 adv = *(const float4*)&g_ad[n * 4];
    int beg = g_rowoff[n], end = g_rowoff[n + 1];
    int cntA = end - beg;

    float4 acc = make_float4(0.f, 0.f, 0.f, 0.f);
    float4 acc2 = acc;
    float4 ss  = acc;

    if (cntA <= 32) {
        bool act = lane < cntA;
        int s = 0;
        float4 ev = make_float4(-1e30f, -1e30f, -1e30f, -1e30f);
        if (act) {
            s = __ldg(&g_csr[beg + lane]);
            float4 a = __ldg((const float4*)&g_as[s * 4]);
            float e;
            e = a.x + adv.x; ev.x = fmaxf(e, NEG * e);
            e = a.y + adv.y; ev.y = fmaxf(e, NEG * e);
            e = a.z + adv.z; ev.z = fmaxf(e, NEG * e);
            e = a.w + adv.w; ev.w = fmaxf(e, NEG * e);
        }
        float4 mx = ev;
#pragma unroll
        for (int off = 16; off; off >>= 1) {
            mx.x = fmaxf(mx.x, __shfl_xor_sync(0xffffffffu, mx.x, off));
            mx.y = fmaxf(mx.y, __shfl_xor_sync(0xffffffffu, mx.y, off));
            mx.z = fmaxf(mx.z, __shfl_xor_sync(0xffffffffu, mx.z, off));
            mx.w = fmaxf(mx.w, __shfl_xor_sync(0xffffffffu, mx.w, off));
        }
        float4 pv = make_float4(0.f, 0.f, 0.f, 0.f);
        if (act) {
            pv.x = __expf(ev.x - mx.x);
            pv.y = __expf(ev.y - mx.y);
            pv.z = __expf(ev.z - mx.z);
            pv.w = __expf(ev.w - mx.w);
            ss = pv;
        }
        s_src[wi][lane] = s;
        s_p[wi][lane] = pv;
        __syncwarp();
        int j = 0;
        for (; j + 2 <= cntA; j += 2) {
            int sj0 = s_src[wi][j];
            int sj1 = s_src[wi][j + 1];
            float pj0 = ((const float*)&s_p[wi][j])[head];
            float pj1 = ((const float*)&s_p[wi][j + 1])[head];
            float4 h0 = __ldg((const float4*)(hbuf + sj0 * 128 + col));
            float4 h1 = __ldg((const float4*)(hbuf + sj1 * 128 + col));
            acc.x = fmaf(pj0, h0.x, acc.x);   acc.y = fmaf(pj0, h0.y, acc.y);
            acc.z = fmaf(pj0, h0.z, acc.z);   acc.w = fmaf(pj0, h0.w, acc.w);
            acc2.x = fmaf(pj1, h1.x, acc2.x); acc2.y = fmaf(pj1, h1.y, acc2.y);
            acc2.z = fmaf(pj1, h1.z, acc2.z); acc2.w = fmaf(pj1, h1.w, acc2.w);
        }
        if (j < cntA) {
            int sj = s_src[wi][j];
            float pj = ((const float*)&s_p[wi][j])[head];
            float4 hv = __ldg((const float4*)(hbuf + sj * 128 + col));
            acc.x = fmaf(pj, hv.x, acc.x);
            acc.y = fmaf(pj, hv.y, acc.y);
            acc.z = fmaf(pj, hv.z, acc.z);
            acc.w = fmaf(pj, hv.w, acc.w);
        }
        __syncwarp();
    } else {
        float4 mx = make_float4(-1e30f, -1e30f, -1e30f, -1e30f);
        for (int p = beg + lane; p < end; p += 32) {
            int s = __ldg(&g_csr[p]);
            float4 a = __ldg((const float4*)&g_as[s * 4]);
            float e;
            e = a.x + adv.x; mx.x = fmaxf(mx.x, fmaxf(e, NEG * e));
            e = a.y + adv.y; mx.y = fmaxf(mx.y, fmaxf(e, NEG * e));
            e = a.z + adv.z; mx.z = fmaxf(mx.z, fmaxf(e, NEG * e));
            e = a.w + adv.w; mx.w = fmaxf(mx.w, fmaxf(e, NEG * e));
        }
#pragma unroll
        for (int off = 16; off; off >>= 1) {
            mx.x = fmaxf(mx.x, __shfl_xor_sync(0xffffffffu, mx.x, off));
            mx.y = fmaxf(mx.y, __shfl_xor_sync(0xffffffffu, mx.y, off));
            mx.z = fmaxf(mx.z, __shfl_xor_sync(0xffffffffu, mx.z, off));
            mx.w = fmaxf(mx.w, __shfl_xor_sync(0xffffffffu, mx.w, off));
        }
        for (int p0 = beg; p0 < end; p0 += 32) {
            int cnt = min(32, end - p0);
            float4 pv = make_float4(0.f, 0.f, 0.f, 0.f);
            int s = 0;
            if (lane < cnt) {
                s = __ldg(&g_csr[p0 + lane]);
                float4 a = __ldg((const float4*)&g_as[s * 4]);
                float e;
                e = a.x + adv.x; e = fmaxf(e, NEG * e); pv.x = __expf(e - mx.x);
                e = a.y + adv.y; e = fmaxf(e, NEG * e); pv.y = __expf(e - mx.y);
                e = a.z + adv.z; e = fmaxf(e, NEG * e); pv.z = __expf(e - mx.z);
                e = a.w + adv.w; e = fmaxf(e, NEG * e); pv.w = __expf(e - mx.w);
                ss.x += pv.x; ss.y += pv.y; ss.z += pv.z; ss.w += pv.w;
            }
            s_src[wi][lane] = s;
            s_p[wi][lane] = pv;
            __syncwarp();
            for (int j = 0; j < cnt; j++) {
                int sj = s_src[wi][j];
                float pj = ((const float*)&s_p[wi][j])[head];
                float4 hv = __ldg((const float4*)(hbuf + sj * 128 + col));
                acc.x = fmaf(pj, hv.x, acc.x);
                acc.y = fmaf(pj, hv.y, acc.y);
                acc.z = fmaf(pj, hv.z, acc.z);
                acc.w = fmaf(pj, hv.w, acc.w);
            }
            __syncwarp();
        }
    }

    acc.x += acc2.x; acc.y += acc2.y; acc.z += acc2.z; acc.w += acc2.w;

#pragma unroll
    for (int off = 16; off; off >>= 1) {
        ss.x += __shfl_xor_sync(0xffffffffu, ss.x, off);
        ss.y += __shfl_xor_sync(0xffffffffu, ss.y, off);
        ss.z += __shfl_xor_sync(0xffffffffu, ss.z, off);
        ss.w += __shfl_xor_sync(0xffffffffu, ss.w, off);
    }
    float sh = (head == 0) ? ss.x : (head == 1) ? ss.y : (head == 2) ? ss.z : ss.w;
    float inv = 1.0f / (sh + 1e-16f);

    float4 b = *(const float4*)(bias + col);
    float4 o;
    o.x = acc.x * inv + b.x; o.x = fmaxf(o.x, NEG * o.x);
    o.y = acc.y * inv + b.y; o.y = fmaxf(o.y, NEG * o.y);
    o.z = acc.z * inv + b.z; o.z = fmaxf(o.z, NEG * o.z);
    o.w = acc.w * inv + b.w; o.w = fmaxf(o.w, NEG * o.w);
    *(float4*)(outbuf + (size_t)n * 128 + col) = o;
}

// ---------------- pooling: segmented over sorted batch ----------------
__global__ __launch_bounds__(512) void pool_kernel(const float* __restrict__ y) {
    __shared__ float sh[3][128];
    int g = blockIdx.x;
    int s = g_goff[g], e = g_goff[g + 1];
    int c = threadIdx.x & 127;
    int r = threadIdx.x >> 7;
    float acc = 0.f;
    for (int i = s + r; i < e; i += 4) acc += y[(size_t)i * 128 + c];
    if (r) sh[r - 1][c] = acc;
    __syncthreads();
    if (!r) g_pool[g * 128 + c] = ((acc + sh[0][c]) + (sh[1][c] + sh[2][c]));
}

// ---------------- head ----------------
__global__ void head_kernel(const float* __restrict__ fc_w, const float* __restrict__ fc_b,
                            const float* __restrict__ bn_g, const float* __restrict__ bn_b,
                            float* __restrict__ out)
{
    int g = blockIdx.x;
    int l = threadIdx.x;
    const float* pr = g_pool + g * HID;
    float s = 0.f;
#pragma unroll 8
    for (int k = 0; k < HID; k++) s = fmaf(pr[k], fc_w[k * LAT + l], s);
    s += fc_b[l];
    const float inv = 0.999995000037499688f;  // 1/sqrt(1 + 1e-5)
    out[g * LAT + l] = bn_g[l] * s * inv + bn_b[l];
}

// ---------------- launch ----------------
extern "C" void kernel_launch(void* const* d_in, const int* in_sizes, int n_in,
                              void* d_out, int out_size)
{
    const float* x       = (const float*)d_in[0];
    const int*   eidx    = (const int*)  d_in[1];
    const int*   batch   = (const int*)  d_in[2];
    const float* W0      = (const float*)d_in[3];
    const float* a_src0  = (const float*)d_in[4];
    const float* a_dst0  = (const float*)d_in[5];
    const float* b0      = (const float*)d_in[6];
    const float* W1      = (const float*)d_in[7];
    const float* a_src1  = (const float*)d_in[8];
    const float* a_dst1  = (const float*)d_in[9];
    const float* b1      = (const float*)d_in[10];
    const float* W2      = (const float*)d_in[11];
    const float* a_src2  = (const float*)d_in[12];
    const float* a_dst2  = (const float*)d_in[13];
    const float* b2      = (const float*)d_in[14];
    const float* fc_w    = (const float*)d_in[15];
    const float* fc_b    = (const float*)d_in[16];
    const float* bn_g    = (const float*)d_in[17];
    const float* bn_b    = (const float*)d_in[18];
    float* out = (float*)d_out;

    const int* src = eidx;
    const int* dst = eidx + EE;

    float *ph, *py;
    __nv_bfloat16 *pw0h, *pw0l, *pw1h, *pw1l, *pw2h, *pw2l;
    cudaGetSymbolAddress((void**)&ph, g_h);
    cudaGetSymbolAddress((void**)&py, g_y);
    cudaGetSymbolAddress((void**)&pw0h, g_w0h);
    cudaGetSymbolAddress((void**)&pw0l, g_w0l);
    cudaGetSymbolAddress((void**)&pw1h, g_w1h);
    cudaGetSymbolAddress((void**)&pw1l, g_w1l);
    cudaGetSymbolAddress((void**)&pw2h, g_w2h);
    cudaGetSymbolAddress((void**)&pw2l, g_w2l);

    const int PREPW_TOT = 128 * 64 + 2 * 128 * 128;
    const int gemm_grid = (NN + 127) / 128;
    const int warp_grid = (NN + 7) / 8;   // 1 warp/node, 8 warps/block

    prepw_kernel<<<(PREPW_TOT + 255) / 256, 256>>>(W0, W1, W2);
    hist_kernel<<<(EE + 255) / 256, 256>>>(dst);
    scan1_kernel<<<SCB, 256>>>();
    gemm_kernel<<<gemm_grid, 256>>>(x, pw0h, pw0l, ph, NN, XK, a_src0, a_dst0);  // slot 4
    scan2_kernel<<<1, 256>>>();
    scan3_kernel<<<SCB, 256>>>();
    scatter_kernel<<<(EE + NN + 255) / 256, 256>>>(src, dst);
    agg_kernel<<<warp_grid, 256>>>(ph, b0, py);

    gemm_kernel<<<gemm_grid, 256>>>(py, pw1h, pw1l, ph, NN, HID, a_src1, a_dst1);
    agg_kernel<<<warp_grid, 256>>>(ph, b1, py);

    gemm_kernel<<<gemm_grid, 256>>>(py, pw2h, pw2l, ph, NN, HID, a_src2, a_dst2);
    agg_kernel<<<warp_grid, 256>>>(ph, b2, py);

    gbound_kernel<<<(NN + 255) / 256, 256>>>(batch);
    pool_kernel<<<GG, 512>>>(py);
    head_kernel<<<GG, LAT>>>(fc_w, fc_b, bn_g, bn_b, out);
}

// round 15
// speedup vs baseline: 1.6783x; 1.0225x over previous
#include <cuda_runtime.h>
#include <cuda_bf16.h>
#include <stdint.h>
#include <math.h>

#define NN 50000
#define EE 800000
#define HID 128
#define GG 128
#define LAT 32
#define NEG 0.2f
#define XK 64
#define SCB 196   // ceil(NN/256) scan blocks

// ---------------- scratch (static device memory; zero-initialized) ----------------
__device__ float g_h[NN * HID];          // gemm output (fp32)
__device__ float g_y[NN * HID];          // agg output (fp32)
__device__ __nv_bfloat16 g_w0h[128 * 64],  g_w0l[128 * 64];    // W^T [n][k] hi/lo
__device__ __nv_bfloat16 g_w1h[128 * 128], g_w1l[128 * 128];
__device__ __nv_bfloat16 g_w2h[128 * 128], g_w2l[128 * 128];
__device__ float g_as[NN * 4];
__device__ float g_ad[NN * 4];
__device__ int   g_deg[NN];              // invariant: zero before/after each launch
__device__ int   g_rowoff[NN + 1];
__device__ int   g_cur[NN];
__device__ int   g_csr[EE + NN];
__device__ int   g_goff[GG + 1];
__device__ int   g_bsum[SCB];
__device__ int   g_boff[SCB];
__device__ float g_pool[GG * HID];

__device__ __forceinline__ void bsplit(float v, __nv_bfloat16& h, __nv_bfloat16& l) {
    h = __float2bfloat16(v);
    l = __float2bfloat16(v - __bfloat162float(h));
}

// ---------------- prep: split W^T into bf16 hi/lo (tiny) ----------------
__global__ void prepw_kernel(const float* __restrict__ W0, const float* __restrict__ W1,
                             const float* __restrict__ W2)
{
    int i = blockIdx.x * blockDim.x + threadIdx.x;
    if (i < 128 * 64) {
        int n = i / 64, k = i % 64;
        bsplit(W0[k * 128 + n], g_w0h[n * 64 + k], g_w0l[n * 64 + k]);
        return;
    }
    i -= 128 * 64;
    if (i < 128 * 128) {
        int n = i >> 7, k = i & 127;
        bsplit(W1[k * 128 + n], g_w1h[n * 128 + k], g_w1l[n * 128 + k]);
        return;
    }
    i -= 128 * 128;
    if (i < 128 * 128) {
        int n = i >> 7, k = i & 127;
        bsplit(W2[k * 128 + n], g_w2h[n * 128 + k], g_w2l[n * 128 + k]);
    }
}

// ---------------- CSR build ----------------
__global__ void hist_kernel(const int* __restrict__ dst) {
    int i = blockIdx.x * blockDim.x + threadIdx.x;
    if (i < EE) atomicAdd(&g_deg[dst[i]], 1);
}

// 3-phase scan of (deg+1)
__global__ void scan1_kernel() {   // per-block sums
    __shared__ int red[256];
    int i = blockIdx.x * 256 + threadIdx.x;
    int v = (i < NN) ? (g_deg[i] + 1) : 0;
    red[threadIdx.x] = v;
    __syncthreads();
#pragma unroll
    for (int off = 128; off; off >>= 1) {
        if (threadIdx.x < off) red[threadIdx.x] += red[threadIdx.x + off];
        __syncthreads();
    }
    if (threadIdx.x == 0) g_bsum[blockIdx.x] = red[0];
}

__global__ void scan2_kernel() {   // exclusive prefix of SCB partials (1 block)
    __shared__ int sc[256];
    int t = threadIdx.x;
    sc[t] = (t < SCB) ? g_bsum[t] : 0;
    __syncthreads();
    for (int off = 1; off < 256; off <<= 1) {
        int v = (t >= off) ? sc[t - off] : 0;
        __syncthreads();
        sc[t] += v;
        __syncthreads();
    }
    if (t < SCB) g_boff[t] = sc[t] - g_bsum[t];   // exclusive
}

__global__ void scan3_kernel() {   // apply offsets, write rowoff/cur, zero deg
    __shared__ int sc[256];
    int t = threadIdx.x;
    int i = blockIdx.x * 256 + t;
    int v = (i < NN) ? (g_deg[i] + 1) : 0;
    sc[t] = v;
    __syncthreads();
    for (int off = 1; off < 256; off <<= 1) {
        int u = (t >= off) ? sc[t - off] : 0;
        __syncthreads();
        sc[t] += u;
        __syncthreads();
    }
    int excl = sc[t] - v + g_boff[blockIdx.x];
    if (i < NN) {
        g_rowoff[i] = excl;
        g_cur[i] = excl;
        g_deg[i] = 0;
        if (i == NN - 1) g_rowoff[NN] = excl + v;
    }
}

__global__ void scatter_kernel(const int* __restrict__ src, const int* __restrict__ dst) {
    int i = blockIdx.x * blockDim.x + threadIdx.x;
    if (i < EE) {
        int d = dst[i];
        int pos = atomicAdd(&g_cur[d], 1);
        g_csr[pos] = src[i];
    } else if (i < EE + NN) {
        int n = i - EE;
        int pos = atomicAdd(&g_cur[n], 1);
        g_csr[pos] = n;
    }
}

__global__ void gbound_kernel(const int* __restrict__ batch) {
    int i = blockIdx.x * blockDim.x + threadIdx.x;
    if (i >= NN) return;
    int b = batch[i];
    int prev = (i == 0) ? -1 : batch[i - 1];
    for (int g = prev + 1; g <= b; g++) g_goff[g] = i;
    if (i == NN - 1) {
        for (int g = b + 1; g <= GG; g++) g_goff[g] = NN;
    }
}

// ---------------- HMMA bf16 split GEMM + fused alpha ----------------------------
#define ASTR 40

#define MMA16816(d, a, b0v, b1v) \
    asm volatile("mma.sync.aligned.m16n8k16.row.col.f32.bf16.bf16.f32 " \
        "{%0,%1,%2,%3}, {%4,%5,%6,%7}, {%8,%9}, {%0,%1,%2,%3};" \
        : "+f"((d)[0]), "+f"((d)[1]), "+f"((d)[2]), "+f"((d)[3]) \
        : "r"((a)[0]), "r"((a)[1]), "r"((a)[2]), "r"((a)[3]), "r"(b0v), "r"(b1v))

__device__ __forceinline__ uint32_t pack_bf2(__nv_bfloat16 lo, __nv_bfloat16 hi) {
    return ((uint32_t)__bfloat16_as_ushort(hi) << 16) | __bfloat16_as_ushort(lo);
}

__global__ __launch_bounds__(256, 2) void gemm_kernel(
    const float* __restrict__ X,
    const __nv_bfloat16* __restrict__ Bh, const __nv_bfloat16* __restrict__ Bl,
    float* __restrict__ Out, int nrows, int K,
    const float* __restrict__ a_src, const float* __restrict__ a_dst)
{
    __shared__ __align__(16) __nv_bfloat16 Ah_s[128 * ASTR];
    __shared__ __align__(16) __nv_bfloat16 Al_s[128 * ASTR];
    __shared__ __align__(16) __nv_bfloat16 Bh_s[128 * ASTR];
    __shared__ __align__(16) __nv_bfloat16 Bl_s[128 * ASTR];
    __shared__ float spart[128][4][2];
    __shared__ float sAs[128], sAd[128];

    int tid = threadIdx.x;
    int wid = tid >> 5, lane = tid & 31;
    int g = lane >> 2, tg = lane & 3;
    int rbase = (wid >> 1) * 32;
    int cbase = (wid & 1) * 64;
    int row0 = blockIdx.x * 128;

    if (tid < 128) { sAs[tid] = a_src[tid]; sAd[tid] = a_dst[tid]; }

    float acc[2][8][4];
#pragma unroll
    for (int mt = 0; mt < 2; mt++)
#pragma unroll
        for (int nt = 0; nt < 8; nt++)
#pragma unroll
            for (int q = 0; q < 4; q++) acc[mt][nt][q] = 0.f;

    int lrow = tid >> 1, lhalf = tid & 1;
    int grow = row0 + lrow;
    bool valid = grow < nrows;
    int k0 = lhalf * 16;

    const int NCH = K >> 5;
    for (int ch = 0; ch < NCH; ch++) {
        {
            const float4* xsrc = (const float4*)(X + (size_t)grow * K + ch * 32 + k0);
            uint32_t* dh = (uint32_t*)&Ah_s[lrow * ASTR + k0];
            uint32_t* dl = (uint32_t*)&Al_s[lrow * ASTR + k0];
#pragma unroll
            for (int j = 0; j < 4; j++) {
                float4 v = make_float4(0.f, 0.f, 0.f, 0.f);
                if (valid) v = __ldg(xsrc + j);
                __nv_bfloat16 h0, h1, h2, h3, l0, l1, l2, l3;
                bsplit(v.x, h0, l0); bsplit(v.y, h1, l1);
                bsplit(v.z, h2, l2); bsplit(v.w, h3, l3);
                dh[j * 2]     = pack_bf2(h0, h1);
                dh[j * 2 + 1] = pack_bf2(h2, h3);
                dl[j * 2]     = pack_bf2(l0, l1);
                dl[j * 2 + 1] = pack_bf2(l2, l3);
            }
        }
        {
            const uint4* ph = (const uint4*)(Bh + (size_t)lrow * K + ch * 32 + k0);
            const uint4* pl = (const uint4*)(Bl + (size_t)lrow * K + ch * 32 + k0);
            uint4 vh0 = __ldg(ph), vh1 = __ldg(ph + 1);
            uint4 vl0 = __ldg(pl), vl1 = __ldg(pl + 1);
            uint4* dh = (uint4*)&Bh_s[lrow * ASTR + k0];
            uint4* dl = (uint4*)&Bl_s[lrow * ASTR + k0];
            dh[0] = vh0; dh[1] = vh1;
            dl[0] = vl0; dl[1] = vl1;
        }
        __syncthreads();

#pragma unroll
        for (int ks = 0; ks < 2; ks++) {
            int kb = ks * 16;
            uint32_t ah[2][4], al[2][4];
#pragma unroll
            for (int mt = 0; mt < 2; mt++) {
                int r = rbase + mt * 16 + g;
                const __nv_bfloat16* ap = &Ah_s[r * ASTR + kb + tg * 2];
                ah[mt][0] = *(const uint32_t*)ap;
                ah[mt][1] = *(const uint32_t*)(ap + 8 * ASTR);
                ah[mt][2] = *(const uint32_t*)(ap + 8);
                ah[mt][3] = *(const uint32_t*)(ap + 8 * ASTR + 8);
                const __nv_bfloat16* lp = &Al_s[r * ASTR + kb + tg * 2];
                al[mt][0] = *(const uint32_t*)lp;
                al[mt][1] = *(const uint32_t*)(lp + 8 * ASTR);
                al[mt][2] = *(const uint32_t*)(lp + 8);
                al[mt][3] = *(const uint32_t*)(lp + 8 * ASTR + 8);
            }
#pragma unroll
            for (int nt = 0; nt < 8; nt++) {
                int nb = cbase + nt * 8 + g;
                const __nv_bfloat16* bp = &Bh_s[nb * ASTR + kb + tg * 2];
                uint32_t bh0 = *(const uint32_t*)bp;
                uint32_t bh1 = *(const uint32_t*)(bp + 8);
                const __nv_bfloat16* qp = &Bl_s[nb * ASTR + kb + tg * 2];
                uint32_t bl0 = *(const uint32_t*)qp;
                uint32_t bl1 = *(const uint32_t*)(qp + 8);
#pragma unroll
                for (int mt = 0; mt < 2; mt++) {
                    MMA16816(acc[mt][nt], ah[mt], bh0, bh1);
                    MMA16816(acc[mt][nt], al[mt], bh0, bh1);
                    MMA16816(acc[mt][nt], ah[mt], bl0, bl1);
                }
            }
        }
        __syncthreads();
    }

    // ---- fused alpha partials ----
    {
        float pA[2][2][2], pD[2][2][2];
#pragma unroll
        for (int mt = 0; mt < 2; mt++)
#pragma unroll
            for (int sb = 0; sb < 2; sb++)
#pragma unroll
                for (int hh = 0; hh < 2; hh++) { pA[mt][sb][hh] = 0.f; pD[mt][sb][hh] = 0.f; }
#pragma unroll
        for (int mt = 0; mt < 2; mt++)
#pragma unroll
            for (int nt = 0; nt < 8; nt++) {
                int hh = nt >> 2;
                int c0 = cbase + nt * 8 + tg * 2;
                float a0 = sAs[c0], a1 = sAs[c0 + 1];
                float d0 = sAd[c0], d1 = sAd[c0 + 1];
                pA[mt][0][hh] += acc[mt][nt][0] * a0 + acc[mt][nt][1] * a1;
                pA[mt][1][hh] += acc[mt][nt][2] * a0 + acc[mt][nt][3] * a1;
                pD[mt][0][hh] += acc[mt][nt][0] * d0 + acc[mt][nt][1] * d1;
                pD[mt][1][hh] += acc[mt][nt][2] * d0 + acc[mt][nt][3] * d1;
            }
#pragma unroll
        for (int mt = 0; mt < 2; mt++)
#pragma unroll
            for (int sb = 0; sb < 2; sb++)
#pragma unroll
                for (int hh = 0; hh < 2; hh++) {
                    float vA = pA[mt][sb][hh], vD = pD[mt][sb][hh];
                    vA += __shfl_xor_sync(0xffffffffu, vA, 1);
                    vA += __shfl_xor_sync(0xffffffffu, vA, 2);
                    vD += __shfl_xor_sync(0xffffffffu, vD, 1);
                    vD += __shfl_xor_sync(0xffffffffu, vD, 2);
                    if (tg == 0) {
                        int row = rbase + mt * 16 + sb * 8 + g;
                        int head = (wid & 1) * 2 + hh;
                        spart[row][head][0] = vA;
                        spart[row][head][1] = vD;
                    }
                }
    }

#pragma unroll
    for (int mt = 0; mt < 2; mt++) {
        int r1 = row0 + rbase + mt * 16 + g;
        int r2 = r1 + 8;
#pragma unroll
        for (int nt = 0; nt < 8; nt++) {
            int c = cbase + nt * 8 + tg * 2;
            if (r1 < nrows)
                *(float2*)&Out[(size_t)r1 * 128 + c] = make_float2(acc[mt][nt][0], acc[mt][nt][1]);
            if (r2 < nrows)
                *(float2*)&Out[(size_t)r2 * 128 + c] = make_float2(acc[mt][nt][2], acc[mt][nt][3]);
        }
    }

    __syncthreads();
    if (tid < 128) {
        int gr = row0 + tid;
        if (gr < nrows) {
            *(float4*)&g_as[gr * 4] = make_float4(spart[tid][0][0], spart[tid][1][0],
                                                  spart[tid][2][0], spart[tid][3][0]);
            *(float4*)&g_ad[gr * 4] = make_float4(spart[tid][0][1], spart[tid][1][1],
                                                  spart[tid][2][1], spart[tid][3][1]);
        }
    }
}

// ---------------- aggregation: one warp per dst node; deg<=32 single-pass -------
__global__ __launch_bounds__(256) void agg_kernel(
    const float* __restrict__ hbuf, const float* __restrict__ bias,
    float* __restrict__ outbuf)
{
    __shared__ int    s_src[8][32];
    __shared__ float4 s_p[8][32];

    int wi = threadIdx.x >> 5;
    int n = (blockIdx.x * blockDim.x + threadIdx.x) >> 5;
    if (n >= NN) return;
    int lane = threadIdx.x & 31;
    int head = lane >> 3;
    int col = head * 32 + (lane & 7) * 4;

    float4 adv = *(const float4*)&g_ad[n * 4];
    int beg = g_rowoff[n], end = g_rowoff[n + 1];
    int cntA = end - beg;

    float4 acc = make_float4(0.f, 0.f, 0.f, 0.f);
    float4 acc2 = acc;
    float4 ss  = acc;

    if (cntA <= 32) {
        bool act = lane < cntA;
        int s = 0;
        float4 ev = make_float4(-1e30f, -1e30f, -1e30f, -1e30f);
        if (act) {
            s = __ldg(&g_csr[beg + lane]);
            float4 a = __ldg((const float4*)&g_as[s * 4]);
            float e;
            e = a.x + adv.x; ev.x = fmaxf(e, NEG * e);
            e = a.y + adv.y; ev.y = fmaxf(e, NEG * e);
            e = a.z + adv.z; ev.z = fmaxf(e, NEG * e);
            e = a.w + adv.w; ev.w = fmaxf(e, NEG * e);
        }
        float4 mx = ev;
#pragma unroll
        for (int off = 16; off; off >>= 1) {
            mx.x = fmaxf(mx.x, __shfl_xor_sync(0xffffffffu, mx.x, off));
            mx.y = fmaxf(mx.y, __shfl_xor_sync(0xffffffffu, mx.y, off));
            mx.z = fmaxf(mx.z, __shfl_xor_sync(0xffffffffu, mx.z, off));
            mx.w = fmaxf(mx.w, __shfl_xor_sync(0xffffffffu, mx.w, off));
        }
        float4 pv = make_float4(0.f, 0.f, 0.f, 0.f);
        if (act) {
            pv.x = __expf(ev.x - mx.x);
            pv.y = __expf(ev.y - mx.y);
            pv.z = __expf(ev.z - mx.z);
            pv.w = __expf(ev.w - mx.w);
            ss = pv;
        }
        s_src[wi][lane] = s;
        s_p[wi][lane] = pv;
        __syncwarp();
        int j = 0;
        for (; j + 2 <= cntA; j += 2) {
            int sj0 = s_src[wi][j];
            int sj1 = s_src[wi][j + 1];
            float pj0 = ((const float*)&s_p[wi][j])[head];
            float pj1 = ((const float*)&s_p[wi][j + 1])[head];
            float4 h0 = __ldg((const float4*)(hbuf + sj0 * 128 + col));
            float4 h1 = __ldg((const float4*)(hbuf + sj1 * 128 + col));
            acc.x = fmaf(pj0, h0.x, acc.x);   acc.y = fmaf(pj0, h0.y, acc.y);
            acc.z = fmaf(pj0, h0.z, acc.z);   acc.w = fmaf(pj0, h0.w, acc.w);
            acc2.x = fmaf(pj1, h1.x, acc2.x); acc2.y = fmaf(pj1, h1.y, acc2.y);
            acc2.z = fmaf(pj1, h1.z, acc2.z); acc2.w = fmaf(pj1, h1.w, acc2.w);
        }
        if (j < cntA) {
            int sj = s_src[wi][j];
            float pj = ((const float*)&s_p[wi][j])[head];
            float4 hv = __ldg((const float4*)(hbuf + sj * 128 + col));
            acc.x = fmaf(pj, hv.x, acc.x);
            acc.y = fmaf(pj, hv.y, acc.y);
            acc.z = fmaf(pj, hv.z, acc.z);
            acc.w = fmaf(pj, hv.w, acc.w);
        }
        __syncwarp();
    } else {
        float4 mx = make_float4(-1e30f, -1e30f, -1e30f, -1e30f);
        for (int p = beg + lane; p < end; p += 32) {
            int s = __ldg(&g_csr[p]);
            float4 a = __ldg((const float4*)&g_as[s * 4]);
            float e;
            e = a.x + adv.x; mx.x = fmaxf(mx.x, fmaxf(e, NEG * e));
            e = a.y + adv.y; mx.y = fmaxf(mx.y, fmaxf(e, NEG * e));
            e = a.z + adv.z; mx.z = fmaxf(mx.z, fmaxf(e, NEG * e));
            e = a.w + adv.w; mx.w = fmaxf(mx.w, fmaxf(e, NEG * e));
        }
#pragma unroll
        for (int off = 16; off; off >>= 1) {
            mx.x = fmaxf(mx.x, __shfl_xor_sync(0xffffffffu, mx.x, off));
            mx.y = fmaxf(mx.y, __shfl_xor_sync(0xffffffffu, mx.y, off));
            mx.z = fmaxf(mx.z, __shfl_xor_sync(0xffffffffu, mx.z, off));
            mx.w = fmaxf(mx.w, __shfl_xor_sync(0xffffffffu, mx.w, off));
        }
        for (int p0 = beg; p0 < end; p0 += 32) {
            int cnt = min(32, end - p0);
            float4 pv = make_float4(0.f, 0.f, 0.f, 0.f);
            int s = 0;
            if (lane < cnt) {
                s = __ldg(&g_csr[p0 + lane]);
                float4 a = __ldg((const float4*)&g_as[s * 4]);
                float e;
                e = a.x + adv.x; e = fmaxf(e, NEG * e); pv.x = __expf(e - mx.x);
                e = a.y + adv.y; e = fmaxf(e, NEG * e); pv.y = __expf(e - mx.y);
                e = a.z + adv.z; e = fmaxf(e, NEG * e); pv.z = __expf(e - mx.z);
                e = a.w + adv.w; e = fmaxf(e, NEG * e); pv.w = __expf(e - mx.w);
                ss.x += pv.x; ss.y += pv.y; ss.z += pv.z; ss.w += pv.w;
            }
            s_src[wi][lane] = s;
            s_p[wi][lane] = pv;
            __syncwarp();
            for (int j = 0; j < cnt; j++) {
                int sj = s_src[wi][j];
                float pj = ((const float*)&s_p[wi][j])[head];
                float4 hv = __ldg((const float4*)(hbuf + sj * 128 + col));
                acc.x = fmaf(pj, hv.x, acc.x);
                acc.y = fmaf(pj, hv.y, acc.y);
                acc.z = fmaf(pj, hv.z, acc.z);
                acc.w = fmaf(pj, hv.w, acc.w);
            }
            __syncwarp();
        }
    }

    acc.x += acc2.x; acc.y += acc2.y; acc.z += acc2.z; acc.w += acc2.w;

#pragma unroll
    for (int off = 16; off; off >>= 1) {
        ss.x += __shfl_xor_sync(0xffffffffu, ss.x, off);
        ss.y += __shfl_xor_sync(0xffffffffu, ss.y, off);
        ss.z += __shfl_xor_sync(0xffffffffu, ss.z, off);
        ss.w += __shfl_xor_sync(0xffffffffu, ss.w, off);
    }
    float sh = (head == 0) ? ss.x : (head == 1) ? ss.y : (head == 2) ? ss.z : ss.w;
    float inv = 1.0f / (sh + 1e-16f);

    float4 b = *(const float4*)(bias + col);
    float4 o;
    o.x = acc.x * inv + b.x; o.x = fmaxf(o.x, NEG * o.x);
    o.y = acc.y * inv + b.y; o.y = fmaxf(o.y, NEG * o.y);
    o.z = acc.z * inv + b.z; o.z = fmaxf(o.z, NEG * o.z);
    o.w = acc.w * inv + b.w; o.w = fmaxf(o.w, NEG * o.w);
    *(float4*)(outbuf + (size_t)n * 128 + col) = o;
}

// ---------------- pooling: segmented over sorted batch ----------------
__global__ __launch_bounds__(512) void pool_kernel(const float* __restrict__ y) {
    __shared__ float sh[3][128];
    int g = blockIdx.x;
    int s = g_goff[g], e = g_goff[g + 1];
    int c = threadIdx.x & 127;
    int r = threadIdx.x >> 7;
    float acc = 0.f;
    for (int i = s + r; i < e; i += 4) acc += y[(size_t)i * 128 + c];
    if (r) sh[r - 1][c] = acc;
    __syncthreads();
    if (!r) g_pool[g * 128 + c] = ((acc + sh[0][c]) + (sh[1][c] + sh[2][c]));
}

// ---------------- head ----------------
__global__ void head_kernel(const float* __restrict__ fc_w, const float* __restrict__ fc_b,
                            const float* __restrict__ bn_g, const float* __restrict__ bn_b,
                            float* __restrict__ out)
{
    int g = blockIdx.x;
    int l = threadIdx.x;
    const float* pr = g_pool + g * HID;
    float s = 0.f;
#pragma unroll 8
    for (int k = 0; k < HID; k++) s = fmaf(pr[k], fc_w[k * LAT + l], s);
    s += fc_b[l];
    const float inv = 0.999995000037499688f;  // 1/sqrt(1 + 1e-5)
    out[g * LAT + l] = bn_g[l] * s * inv + bn_b[l];
}

// ---------------- launch ----------------
extern "C" void kernel_launch(void* const* d_in, const int* in_sizes, int n_in,
                              void* d_out, int out_size)
{
    const float* x       = (const float*)d_in[0];
    const int*   eidx    = (const int*)  d_in[1];
    const int*   batch   = (const int*)  d_in[2];
    const float* W0      = (const float*)d_in[3];
    const float* a_src0  = (const float*)d_in[4];
    const float* a_dst0  = (const float*)d_in[5];
    const float* b0      = (const float*)d_in[6];
    const float* W1      = (const float*)d_in[7];
    const float* a_src1  = (const float*)d_in[8];
    const float* a_dst1  = (const float*)d_in[9];
    const float* b1      = (const float*)d_in[10];
    const float* W2      = (const float*)d_in[11];
    const float* a_src2  = (const float*)d_in[12];
    const float* a_dst2  = (const float*)d_in[13];
    const float* b2      = (const float*)d_in[14];
    const float* fc_w    = (const float*)d_in[15];
    const float* fc_b    = (const float*)d_in[16];
    const float* bn_g    = (const float*)d_in[17];
    const float* bn_b    = (const float*)d_in[18];
    float* out = (float*)d_out;

    const int* src = eidx;
    const int* dst = eidx + EE;

    float *ph, *py;
    __nv_bfloat16 *pw0h, *pw0l, *pw1h, *pw1l, *pw2h, *pw2l;
    cudaGetSymbolAddress((void**)&ph, g_h);
    cudaGetSymbolAddress((void**)&py, g_y);
    cudaGetSymbolAddress((void**)&pw0h, g_w0h);
    cudaGetSymbolAddress((void**)&pw0l, g_w0l);
    cudaGetSymbolAddress((void**)&pw1h, g_w1h);
    cudaGetSymbolAddress((void**)&pw1l, g_w1l);
    cudaGetSymbolAddress((void**)&pw2h, g_w2h);
    cudaGetSymbolAddress((void**)&pw2l, g_w2l);

    // persistent side stream + events (host objects, created once; every call
    // issues the identical fork-join launch pattern -> replay-deterministic)
    static cudaStream_t s_side = nullptr;
    static cudaEvent_t s_fork = nullptr, s_join = nullptr;
    if (s_side == nullptr) {
        cudaStreamCreateWithFlags(&s_side, cudaStreamNonBlocking);
        cudaEventCreateWithFlags(&s_fork, cudaEventDisableTiming);
        cudaEventCreateWithFlags(&s_join, cudaEventDisableTiming);
    }

    const int PREPW_TOT = 128 * 64 + 2 * 128 * 128;
    const int gemm_grid = (NN + 127) / 128;
    const int warp_grid = (NN + 7) / 8;   // 1 warp/node, 8 warps/block

    // ---- fork: CSR build chain on side stream, prepw+gemm0 on main ----
    cudaEventRecord(s_fork, 0);
    cudaStreamWaitEvent(s_side, s_fork, 0);

    hist_kernel<<<(EE + 255) / 256, 256, 0, s_side>>>(dst);
    scan1_kernel<<<SCB, 256, 0, s_side>>>();
    scan2_kernel<<<1, 256, 0, s_side>>>();
    scan3_kernel<<<SCB, 256, 0, s_side>>>();
    scatter_kernel<<<(EE + NN + 255) / 256, 256, 0, s_side>>>(src, dst);
    gbound_kernel<<<(NN + 255) / 256, 256, 0, s_side>>>(batch);
    cudaEventRecord(s_join, s_side);

    prepw_kernel<<<(PREPW_TOT + 255) / 256, 256>>>(W0, W1, W2);
    gemm_kernel<<<gemm_grid, 256>>>(x, pw0h, pw0l, ph, NN, XK, a_src0, a_dst0);

    // ---- join before agg0 (needs CSR) ----
    cudaStreamWaitEvent(0, s_join, 0);
    agg_kernel<<<warp_grid, 256>>>(ph, b0, py);

    gemm_kernel<<<gemm_grid, 256>>>(py, pw1h, pw1l, ph, NN, HID, a_src1, a_dst1);
    agg_kernel<<<warp_grid, 256>>>(ph, b1, py);

    gemm_kernel<<<gemm_grid, 256>>>(py, pw2h, pw2l, ph, NN, HID, a_src2, a_dst2);
    agg_kernel<<<warp_grid, 256>>>(ph, b2, py);

    pool_kernel<<<GG, 512>>>(py);
    head_kernel<<<GG, LAT>>>(fc_w, fc_b, bn_g, bn_b, out);
}

// round 16
// speedup vs baseline: 1.8728x; 1.1159x over previous
#include <cuda_runtime.h>
#include <cuda_bf16.h>
#include <cuda_fp16.h>
#include <stdint.h>
#include <math.h>

#define NN 50000
#define EE 800000
#define HID 128
#define GG 128
#define LAT 32
#define NEG 0.2f
#define XK 64
#define SCB 196   // ceil(NN/256) scan blocks

// ---------------- scratch (static device memory; zero-initialized) ----------------
__device__ uint32_t g_h[NN * 64];        // gemm output, packed fp16x2 (agg gather)
__device__ float g_y[NN * HID];          // agg output (fp32)
__device__ __nv_bfloat16 g_w0h[128 * 64],  g_w0l[128 * 64];    // W^T [n][k] hi/lo
__device__ __nv_bfloat16 g_w1h[128 * 128], g_w1l[128 * 128];
__device__ __nv_bfloat16 g_w2h[128 * 128], g_w2l[128 * 128];
__device__ float g_as[NN * 4];
__device__ float g_ad[NN * 4];
__device__ int   g_deg[NN];              // invariant: zero before/after each launch
__device__ int   g_rowoff[NN + 1];
__device__ int   g_cur[NN];
__device__ int   g_csr[EE + NN];
__device__ int   g_goff[GG + 1];
__device__ int   g_bsum[SCB];
__device__ int   g_boff[SCB];
__device__ float g_pool[GG * HID];

__device__ __forceinline__ void bsplit(float v, __nv_bfloat16& h, __nv_bfloat16& l) {
    h = __float2bfloat16(v);
    l = __float2bfloat16(v - __bfloat162float(h));
}

// ---------------- prep: split W^T into bf16 hi/lo (tiny) ----------------
__global__ void prepw_kernel(const float* __restrict__ W0, const float* __restrict__ W1,
                             const float* __restrict__ W2)
{
    int i = blockIdx.x * blockDim.x + threadIdx.x;
    if (i < 128 * 64) {
        int n = i / 64, k = i % 64;
        bsplit(W0[k * 128 + n], g_w0h[n * 64 + k], g_w0l[n * 64 + k]);
        return;
    }
    i -= 128 * 64;
    if (i < 128 * 128) {
        int n = i >> 7, k = i & 127;
        bsplit(W1[k * 128 + n], g_w1h[n * 128 + k], g_w1l[n * 128 + k]);
        return;
    }
    i -= 128 * 128;
    if (i < 128 * 128) {
        int n = i >> 7, k = i & 127;
        bsplit(W2[k * 128 + n], g_w2h[n * 128 + k], g_w2l[n * 128 + k]);
    }
}

// ---------------- CSR build ----------------
__global__ void hist_kernel(const int* __restrict__ dst) {
    int i = blockIdx.x * blockDim.x + threadIdx.x;
    if (i < EE) atomicAdd(&g_deg[dst[i]], 1);
}

__global__ void scan1_kernel() {
    __shared__ int red[256];
    int i = blockIdx.x * 256 + threadIdx.x;
    int v = (i < NN) ? (g_deg[i] + 1) : 0;
    red[threadIdx.x] = v;
    __syncthreads();
#pragma unroll
    for (int off = 128; off; off >>= 1) {
        if (threadIdx.x < off) red[threadIdx.x] += red[threadIdx.x + off];
        __syncthreads();
    }
    if (threadIdx.x == 0) g_bsum[blockIdx.x] = red[0];
}

__global__ void scan2_kernel() {
    __shared__ int sc[256];
    int t = threadIdx.x;
    sc[t] = (t < SCB) ? g_bsum[t] : 0;
    __syncthreads();
    for (int off = 1; off < 256; off <<= 1) {
        int v = (t >= off) ? sc[t - off] : 0;
        __syncthreads();
        sc[t] += v;
        __syncthreads();
    }
    if (t < SCB) g_boff[t] = sc[t] - g_bsum[t];
}

__global__ void scan3_kernel() {
    __shared__ int sc[256];
    int t = threadIdx.x;
    int i = blockIdx.x * 256 + t;
    int v = (i < NN) ? (g_deg[i] + 1) : 0;
    sc[t] = v;
    __syncthreads();
    for (int off = 1; off < 256; off <<= 1) {
        int u = (t >= off) ? sc[t - off] : 0;
        __syncthreads();
        sc[t] += u;
        __syncthreads();
    }
    int excl = sc[t] - v + g_boff[blockIdx.x];
    if (i < NN) {
        g_rowoff[i] = excl;
        g_cur[i] = excl;
        g_deg[i] = 0;
        if (i == NN - 1) g_rowoff[NN] = excl + v;
    }
}

__global__ void scatter_kernel(const int* __restrict__ src, const int* __restrict__ dst) {
    int i = blockIdx.x * blockDim.x + threadIdx.x;
    if (i < EE) {
        int d = dst[i];
        int pos = atomicAdd(&g_cur[d], 1);
        g_csr[pos] = src[i];
    } else if (i < EE + NN) {
        int n = i - EE;
        int pos = atomicAdd(&g_cur[n], 1);
        g_csr[pos] = n;
    }
}

__global__ void gbound_kernel(const int* __restrict__ batch) {
    int i = blockIdx.x * blockDim.x + threadIdx.x;
    if (i >= NN) return;
    int b = batch[i];
    int prev = (i == 0) ? -1 : batch[i - 1];
    for (int g = prev + 1; g <= b; g++) g_goff[g] = i;
    if (i == NN - 1) {
        for (int g = b + 1; g <= GG; g++) g_goff[g] = NN;
    }
}

// ---------------- HMMA bf16 split GEMM + fused alpha; fp16x2 output -------------
#define ASTR 40

#define MMA16816(d, a, b0v, b1v) \
    asm volatile("mma.sync.aligned.m16n8k16.row.col.f32.bf16.bf16.f32 " \
        "{%0,%1,%2,%3}, {%4,%5,%6,%7}, {%8,%9}, {%0,%1,%2,%3};" \
        : "+f"((d)[0]), "+f"((d)[1]), "+f"((d)[2]), "+f"((d)[3]) \
        : "r"((a)[0]), "r"((a)[1]), "r"((a)[2]), "r"((a)[3]), "r"(b0v), "r"(b1v))

__device__ __forceinline__ uint32_t pack_bf2(__nv_bfloat16 lo, __nv_bfloat16 hi) {
    return ((uint32_t)__bfloat16_as_ushort(hi) << 16) | __bfloat16_as_ushort(lo);
}

__global__ __launch_bounds__(256, 2) void gemm_kernel(
    const float* __restrict__ X,
    const __nv_bfloat16* __restrict__ Bh, const __nv_bfloat16* __restrict__ Bl,
    uint32_t* __restrict__ Out, int nrows, int K,
    const float* __restrict__ a_src, const float* __restrict__ a_dst)
{
    __shared__ __align__(16) __nv_bfloat16 Ah_s[128 * ASTR];
    __shared__ __align__(16) __nv_bfloat16 Al_s[128 * ASTR];
    __shared__ __align__(16) __nv_bfloat16 Bh_s[128 * ASTR];
    __shared__ __align__(16) __nv_bfloat16 Bl_s[128 * ASTR];
    __shared__ float spart[128][4][2];
    __shared__ float sAs[128], sAd[128];

    int tid = threadIdx.x;
    int wid = tid >> 5, lane = tid & 31;
    int g = lane >> 2, tg = lane & 3;
    int rbase = (wid >> 1) * 32;
    int cbase = (wid & 1) * 64;
    int row0 = blockIdx.x * 128;

    if (tid < 128) { sAs[tid] = a_src[tid]; sAd[tid] = a_dst[tid]; }

    float acc[2][8][4];
#pragma unroll
    for (int mt = 0; mt < 2; mt++)
#pragma unroll
        for (int nt = 0; nt < 8; nt++)
#pragma unroll
            for (int q = 0; q < 4; q++) acc[mt][nt][q] = 0.f;

    int lrow = tid >> 1, lhalf = tid & 1;
    int grow = row0 + lrow;
    bool valid = grow < nrows;
    int k0 = lhalf * 16;

    const int NCH = K >> 5;
    for (int ch = 0; ch < NCH; ch++) {
        {
            const float4* xsrc = (const float4*)(X + (size_t)grow * K + ch * 32 + k0);
            uint32_t* dh = (uint32_t*)&Ah_s[lrow * ASTR + k0];
            uint32_t* dl = (uint32_t*)&Al_s[lrow * ASTR + k0];
#pragma unroll
            for (int j = 0; j < 4; j++) {
                float4 v = make_float4(0.f, 0.f, 0.f, 0.f);
                if (valid) v = __ldg(xsrc + j);
                __nv_bfloat16 h0, h1, h2, h3, l0, l1, l2, l3;
                bsplit(v.x, h0, l0); bsplit(v.y, h1, l1);
                bsplit(v.z, h2, l2); bsplit(v.w, h3, l3);
                dh[j * 2]     = pack_bf2(h0, h1);
                dh[j * 2 + 1] = pack_bf2(h2, h3);
                dl[j * 2]     = pack_bf2(l0, l1);
                dl[j * 2 + 1] = pack_bf2(l2, l3);
            }
        }
        {
            const uint4* ph = (const uint4*)(Bh + (size_t)lrow * K + ch * 32 + k0);
            const uint4* pl = (const uint4*)(Bl + (size_t)lrow * K + ch * 32 + k0);
            uint4 vh0 = __ldg(ph), vh1 = __ldg(ph + 1);
            uint4 vl0 = __ldg(pl), vl1 = __ldg(pl + 1);
            uint4* dh = (uint4*)&Bh_s[lrow * ASTR + k0];
            uint4* dl = (uint4*)&Bl_s[lrow * ASTR + k0];
            dh[0] = vh0; dh[1] = vh1;
            dl[0] = vl0; dl[1] = vl1;
        }
        __syncthreads();

#pragma unroll
        for (int ks = 0; ks < 2; ks++) {
            int kb = ks * 16;
            uint32_t ah[2][4], al[2][4];
#pragma unroll
            for (int mt = 0; mt < 2; mt++) {
                int r = rbase + mt * 16 + g;
                const __nv_bfloat16* ap = &Ah_s[r * ASTR + kb + tg * 2];
                ah[mt][0] = *(const uint32_t*)ap;
                ah[mt][1] = *(const uint32_t*)(ap + 8 * ASTR);
                ah[mt][2] = *(const uint32_t*)(ap + 8);
                ah[mt][3] = *(const uint32_t*)(ap + 8 * ASTR + 8);
                const __nv_bfloat16* lp = &Al_s[r * ASTR + kb + tg * 2];
                al[mt][0] = *(const uint32_t*)lp;
                al[mt][1] = *(const uint32_t*)(lp + 8 * ASTR);
                al[mt][2] = *(const uint32_t*)(lp + 8);
                al[mt][3] = *(const uint32_t*)(lp + 8 * ASTR + 8);
            }
#pragma unroll
            for (int nt = 0; nt < 8; nt++) {
                int nb = cbase + nt * 8 + g;
                const __nv_bfloat16* bp = &Bh_s[nb * ASTR + kb + tg * 2];
                uint32_t bh0 = *(const uint32_t*)bp;
                uint32_t bh1 = *(const uint32_t*)(bp + 8);
                const __nv_bfloat16* qp = &Bl_s[nb * ASTR + kb + tg * 2];
                uint32_t bl0 = *(const uint32_t*)qp;
                uint32_t bl1 = *(const uint32_t*)(qp + 8);
#pragma unroll
                for (int mt = 0; mt < 2; mt++) {
                    MMA16816(acc[mt][nt], ah[mt], bh0, bh1);
                    MMA16816(acc[mt][nt], al[mt], bh0, bh1);
                    MMA16816(acc[mt][nt], ah[mt], bl0, bl1);
                }
            }
        }
        __syncthreads();
    }

    // ---- fused alpha partials (fp32 accumulators) ----
    {
        float pA[2][2][2], pD[2][2][2];
#pragma unroll
        for (int mt = 0; mt < 2; mt++)
#pragma unroll
            for (int sb = 0; sb < 2; sb++)
#pragma unroll
                for (int hh = 0; hh < 2; hh++) { pA[mt][sb][hh] = 0.f; pD[mt][sb][hh] = 0.f; }
#pragma unroll
        for (int mt = 0; mt < 2; mt++)
#pragma unroll
            for (int nt = 0; nt < 8; nt++) {
                int hh = nt >> 2;
                int c0 = cbase + nt * 8 + tg * 2;
                float a0 = sAs[c0], a1 = sAs[c0 + 1];
                float d0 = sAd[c0], d1 = sAd[c0 + 1];
                pA[mt][0][hh] += acc[mt][nt][0] * a0 + acc[mt][nt][1] * a1;
                pA[mt][1][hh] += acc[mt][nt][2] * a0 + acc[mt][nt][3] * a1;
                pD[mt][0][hh] += acc[mt][nt][0] * d0 + acc[mt][nt][1] * d1;
                pD[mt][1][hh] += acc[mt][nt][2] * d0 + acc[mt][nt][3] * d1;
            }
#pragma unroll
        for (int mt = 0; mt < 2; mt++)
#pragma unroll
            for (int sb = 0; sb < 2; sb++)
#pragma unroll
                for (int hh = 0; hh < 2; hh++) {
                    float vA = pA[mt][sb][hh], vD = pD[mt][sb][hh];
                    vA += __shfl_xor_sync(0xffffffffu, vA, 1);
                    vA += __shfl_xor_sync(0xffffffffu, vA, 2);
                    vD += __shfl_xor_sync(0xffffffffu, vD, 1);
                    vD += __shfl_xor_sync(0xffffffffu, vD, 2);
                    if (tg == 0) {
                        int row = rbase + mt * 16 + sb * 8 + g;
                        int head = (wid & 1) * 2 + hh;
                        spart[row][head][0] = vA;
                        spart[row][head][1] = vD;
                    }
                }
    }

    // ---- store Out as packed fp16x2 (2 channels per uint32) ----
#pragma unroll
    for (int mt = 0; mt < 2; mt++) {
        int r1 = row0 + rbase + mt * 16 + g;
        int r2 = r1 + 8;
#pragma unroll
        for (int nt = 0; nt < 8; nt++) {
            int cw = (cbase >> 1) + nt * 4 + tg;   // uint32 index within row (64 per row)
            if (r1 < nrows) {
                __half2 p = __floats2half2_rn(acc[mt][nt][0], acc[mt][nt][1]);
                Out[(size_t)r1 * 64 + cw] = *(uint32_t*)&p;
            }
            if (r2 < nrows) {
                __half2 p = __floats2half2_rn(acc[mt][nt][2], acc[mt][nt][3]);
                Out[(size_t)r2 * 64 + cw] = *(uint32_t*)&p;
            }
        }
    }

    __syncthreads();
    if (tid < 128) {
        int gr = row0 + tid;
        if (gr < nrows) {
            *(float4*)&g_as[gr * 4] = make_float4(spart[tid][0][0], spart[tid][1][0],
                                                  spart[tid][2][0], spart[tid][3][0]);
            *(float4*)&g_ad[gr * 4] = make_float4(spart[tid][0][1], spart[tid][1][1],
                                                  spart[tid][2][1], spart[tid][3][1]);
        }
    }
}

// ---------------- aggregation: one warp per dst node; fp16x2 h gather -----------
__global__ __launch_bounds__(256) void agg_kernel(
    const uint32_t* __restrict__ hbuf, const float* __restrict__ bias,
    float* __restrict__ outbuf)
{
    __shared__ int    s_src[8][32];
    __shared__ float4 s_p[8][32];

    int wi = threadIdx.x >> 5;
    int n = (blockIdx.x * blockDim.x + threadIdx.x) >> 5;
    if (n >= NN) return;
    int lane = threadIdx.x & 31;
    int head = lane >> 3;
    int cw = head * 16 + (lane & 7) * 2;   // uint32 index: channels cw*2..cw*2+3

    float4 adv = *(const float4*)&g_ad[n * 4];
    int beg = g_rowoff[n], end = g_rowoff[n + 1];
    int cntA = end - beg;

    float4 acc = make_float4(0.f, 0.f, 0.f, 0.f);
    float4 acc2 = acc;
    float4 ss  = acc;

    if (cntA <= 32) {
        bool act = lane < cntA;
        int s = 0;
        float4 ev = make_float4(-1e30f, -1e30f, -1e30f, -1e30f);
        if (act) {
            s = __ldg(&g_csr[beg + lane]);
            float4 a = __ldg((const float4*)&g_as[s * 4]);
            float e;
            e = a.x + adv.x; ev.x = fmaxf(e, NEG * e);
            e = a.y + adv.y; ev.y = fmaxf(e, NEG * e);
            e = a.z + adv.z; ev.z = fmaxf(e, NEG * e);
            e = a.w + adv.w; ev.w = fmaxf(e, NEG * e);
        }
        float4 mx = ev;
#pragma unroll
        for (int off = 16; off; off >>= 1) {
            mx.x = fmaxf(mx.x, __shfl_xor_sync(0xffffffffu, mx.x, off));
            mx.y = fmaxf(mx.y, __shfl_xor_sync(0xffffffffu, mx.y, off));
            mx.z = fmaxf(mx.z, __shfl_xor_sync(0xffffffffu, mx.z, off));
            mx.w = fmaxf(mx.w, __shfl_xor_sync(0xffffffffu, mx.w, off));
        }
        float4 pv = make_float4(0.f, 0.f, 0.f, 0.f);
        if (act) {
            pv.x = __expf(ev.x - mx.x);
            pv.y = __expf(ev.y - mx.y);
            pv.z = __expf(ev.z - mx.z);
            pv.w = __expf(ev.w - mx.w);
            ss = pv;
        }
        s_src[wi][lane] = s;
        s_p[wi][lane] = pv;
        __syncwarp();
        int j = 0;
        for (; j + 2 <= cntA; j += 2) {
            int sj0 = s_src[wi][j];
            int sj1 = s_src[wi][j + 1];
            float pj0 = ((const float*)&s_p[wi][j])[head];
            float pj1 = ((const float*)&s_p[wi][j + 1])[head];
            uint2 q0 = __ldg((const uint2*)(hbuf + (size_t)sj0 * 64 + cw));
            uint2 q1 = __ldg((const uint2*)(hbuf + (size_t)sj1 * 64 + cw));
            float2 f0a = __half22float2(*(__half2*)&q0.x);
            float2 f0b = __half22float2(*(__half2*)&q0.y);
            float2 f1a = __half22float2(*(__half2*)&q1.x);
            float2 f1b = __half22float2(*(__half2*)&q1.y);
            acc.x = fmaf(pj0, f0a.x, acc.x);   acc.y = fmaf(pj0, f0a.y, acc.y);
            acc.z = fmaf(pj0, f0b.x, acc.z);   acc.w = fmaf(pj0, f0b.y, acc.w);
            acc2.x = fmaf(pj1, f1a.x, acc2.x); acc2.y = fmaf(pj1, f1a.y, acc2.y);
            acc2.z = fmaf(pj1, f1b.x, acc2.z); acc2.w = fmaf(pj1, f1b.y, acc2.w);
        }
        if (j < cntA) {
            int sj = s_src[wi][j];
            float pj = ((const float*)&s_p[wi][j])[head];
            uint2 q = __ldg((const uint2*)(hbuf + (size_t)sj * 64 + cw));
            float2 fa = __half22float2(*(__half2*)&q.x);
            float2 fb = __half22float2(*(__half2*)&q.y);
            acc.x = fmaf(pj, fa.x, acc.x);
            acc.y = fmaf(pj, fa.y, acc.y);
            acc.z = fmaf(pj, fb.x, acc.z);
            acc.w = fmaf(pj, fb.y, acc.w);
        }
        __syncwarp();
    } else {
        float4 mx = make_float4(-1e30f, -1e30f, -1e30f, -1e30f);
        for (int p = beg + lane; p < end; p += 32) {
            int s = __ldg(&g_csr[p]);
            float4 a = __ldg((const float4*)&g_as[s * 4]);
            float e;
            e = a.x + adv.x; mx.x = fmaxf(mx.x, fmaxf(e, NEG * e));
            e = a.y + adv.y; mx.y = fmaxf(mx.y, fmaxf(e, NEG * e));
            e = a.z + adv.z; mx.z = fmaxf(mx.z, fmaxf(e, NEG * e));
            e = a.w + adv.w; mx.w = fmaxf(mx.w, fmaxf(e, NEG * e));
        }
#pragma unroll
        for (int off = 16; off; off >>= 1) {
            mx.x = fmaxf(mx.x, __shfl_xor_sync(0xffffffffu, mx.x, off));
            mx.y = fmaxf(mx.y, __shfl_xor_sync(0xffffffffu, mx.y, off));
            mx.z = fmaxf(mx.z, __shfl_xor_sync(0xffffffffu, mx.z, off));
            mx.w = fmaxf(mx.w, __shfl_xor_sync(0xffffffffu, mx.w, off));
        }
        for (int p0 = beg; p0 < end; p0 += 32) {
            int cnt = min(32, end - p0);
            float4 pv = make_float4(0.f, 0.f, 0.f, 0.f);
            int s = 0;
            if (lane < cnt) {
                s = __ldg(&g_csr[p0 + lane]);
                float4 a = __ldg((const float4*)&g_as[s * 4]);
                float e;
                e = a.x + adv.x; e = fmaxf(e, NEG * e); pv.x = __expf(e - mx.x);
                e = a.y + adv.y; e = fmaxf(e, NEG * e); pv.y = __expf(e - mx.y);
                e = a.z + adv.z; e = fmaxf(e, NEG * e); pv.z = __expf(e - mx.z);
                e = a.w + adv.w; e = fmaxf(e, NEG * e); pv.w = __expf(e - mx.w);
                ss.x += pv.x; ss.y += pv.y; ss.z += pv.z; ss.w += pv.w;
            }
            s_src[wi][lane] = s;
            s_p[wi][lane] = pv;
            __syncwarp();
            for (int j = 0; j < cnt; j++) {
                int sj = s_src[wi][j];
                float pj = ((const float*)&s_p[wi][j])[head];
                uint2 q = __ldg((const uint2*)(hbuf + (size_t)sj * 64 + cw));
                float2 fa = __half22float2(*(__half2*)&q.x);
                float2 fb = __half22float2(*(__half2*)&q.y);
                acc.x = fmaf(pj, fa.x, acc.x);
                acc.y = fmaf(pj, fa.y, acc.y);
                acc.z = fmaf(pj, fb.x, acc.z);
                acc.w = fmaf(pj, fb.y, acc.w);
            }
            __syncwarp();
        }
    }

    acc.x += acc2.x; acc.y += acc2.y; acc.z += acc2.z; acc.w += acc2.w;

#pragma unroll
    for (int off = 16; off; off >>= 1) {
        ss.x += __shfl_xor_sync(0xffffffffu, ss.x, off);
        ss.y += __shfl_xor_sync(0xffffffffu, ss.y, off);
        ss.z += __shfl_xor_sync(0xffffffffu, ss.z, off);
        ss.w += __shfl_xor_sync(0xffffffffu, ss.w, off);
    }
    float sh = (head == 0) ? ss.x : (head == 1) ? ss.y : (head == 2) ? ss.z : ss.w;
    float inv = 1.0f / (sh + 1e-16f);

    int col = head * 32 + (lane & 7) * 4;
    float4 b = *(const float4*)(bias + col);
    float4 o;
    o.x = acc.x * inv + b.x; o.x = fmaxf(o.x, NEG * o.x);
    o.y = acc.y * inv + b.y; o.y = fmaxf(o.y, NEG * o.y);
    o.z = acc.z * inv + b.z; o.z = fmaxf(o.z, NEG * o.z);
    o.w = acc.w * inv + b.w; o.w = fmaxf(o.w, NEG * o.w);
    *(float4*)(outbuf + (size_t)n * 128 + col) = o;
}

// ---------------- pooling: segmented over sorted batch ----------------
__global__ __launch_bounds__(512) void pool_kernel(const float* __restrict__ y) {
    __shared__ float sh[3][128];
    int g = blockIdx.x;
    int s = g_goff[g], e = g_goff[g + 1];
    int c = threadIdx.x & 127;
    int r = threadIdx.x >> 7;
    float acc = 0.f;
    for (int i = s + r; i < e; i += 4) acc += y[(size_t)i * 128 + c];
    if (r) sh[r - 1][c] = acc;
    __syncthreads();
    if (!r) g_pool[g * 128 + c] = ((acc + sh[0][c]) + (sh[1][c] + sh[2][c]));
}

// ---------------- head ----------------
__global__ void head_kernel(const float* __restrict__ fc_w, const float* __restrict__ fc_b,
                            const float* __restrict__ bn_g, const float* __restrict__ bn_b,
                            float* __restrict__ out)
{
    int g = blockIdx.x;
    int l = threadIdx.x;
    const float* pr = g_pool + g * HID;
    float s = 0.f;
#pragma unroll 8
    for (int k = 0; k < HID; k++) s = fmaf(pr[k], fc_w[k * LAT + l], s);
    s += fc_b[l];
    const float inv = 0.999995000037499688f;  // 1/sqrt(1 + 1e-5)
    out[g * LAT + l] = bn_g[l] * s * inv + bn_b[l];
}

// ---------------- launch ----------------
extern "C" void kernel_launch(void* const* d_in, const int* in_sizes, int n_in,
                              void* d_out, int out_size)
{
    const float* x       = (const float*)d_in[0];
    const int*   eidx    = (const int*)  d_in[1];
    const int*   batch   = (const int*)  d_in[2];
    const float* W0      = (const float*)d_in[3];
    const float* a_src0  = (const float*)d_in[4];
    const float* a_dst0  = (const float*)d_in[5];
    const float* b0      = (const float*)d_in[6];
    const float* W1      = (const float*)d_in[7];
    const float* a_src1  = (const float*)d_in[8];
    const float* a_dst1  = (const float*)d_in[9];
    const float* b1      = (const float*)d_in[10];
    const float* W2      = (const float*)d_in[11];
    const float* a_src2  = (const float*)d_in[12];
    const float* a_dst2  = (const float*)d_in[13];
    const float* b2      = (const float*)d_in[14];
    const float* fc_w    = (const float*)d_in[15];
    const float* fc_b    = (const float*)d_in[16];
    const float* bn_g    = (const float*)d_in[17];
    const float* bn_b    = (const float*)d_in[18];
    float* out = (float*)d_out;

    const int* src = eidx;
    const int* dst = eidx + EE;

    uint32_t* ph;
    float* py;
    __nv_bfloat16 *pw0h, *pw0l, *pw1h, *pw1l, *pw2h, *pw2l;
    cudaGetSymbolAddress((void**)&ph, g_h);
    cudaGetSymbolAddress((void**)&py, g_y);
    cudaGetSymbolAddress((void**)&pw0h, g_w0h);
    cudaGetSymbolAddress((void**)&pw0l, g_w0l);
    cudaGetSymbolAddress((void**)&pw1h, g_w1h);
    cudaGetSymbolAddress((void**)&pw1l, g_w1l);
    cudaGetSymbolAddress((void**)&pw2h, g_w2h);
    cudaGetSymbolAddress((void**)&pw2l, g_w2l);

    static cudaStream_t s_side = nullptr;
    static cudaEvent_t s_fork = nullptr, s_join = nullptr;
    if (s_side == nullptr) {
        cudaStreamCreateWithFlags(&s_side, cudaStreamNonBlocking);
        cudaEventCreateWithFlags(&s_fork, cudaEventDisableTiming);
        cudaEventCreateWithFlags(&s_join, cudaEventDisableTiming);
    }

    const int PREPW_TOT = 128 * 64 + 2 * 128 * 128;
    const int gemm_grid = (NN + 127) / 128;
    const int warp_grid = (NN + 7) / 8;

    cudaEventRecord(s_fork, 0);
    cudaStreamWaitEvent(s_side, s_fork, 0);

    hist_kernel<<<(EE + 255) / 256, 256, 0, s_side>>>(dst);
    scan1_kernel<<<SCB, 256, 0, s_side>>>();
    scan2_kernel<<<1, 256, 0, s_side>>>();
    scan3_kernel<<<SCB, 256, 0, s_side>>>();
    scatter_kernel<<<(EE + NN + 255) / 256, 256, 0, s_side>>>(src, dst);
    gbound_kernel<<<(NN + 255) / 256, 256, 0, s_side>>>(batch);
    cudaEventRecord(s_join, s_side);

    prepw_kernel<<<(PREPW_TOT + 255) / 256, 256>>>(W0, W1, W2);
    gemm_kernel<<<gemm_grid, 256>>>(x, pw0h, pw0l, ph, NN, XK, a_src0, a_dst0);

    cudaStreamWaitEvent(0, s_join, 0);
    agg_kernel<<<warp_grid, 256>>>(ph, b0, py);

    gemm_kernel<<<gemm_grid, 256>>>(py, pw1h, pw1l, ph, NN, HID, a_src1, a_dst1);
    agg_kernel<<<warp_grid, 256>>>(ph, b1, py);

    gemm_kernel<<<gemm_grid, 256>>>(py, pw2h, pw2l, ph, NN, HID, a_src2, a_dst2);
    agg_kernel<<<warp_grid, 256>>>(ph, b2, py);

    pool_kernel<<<GG, 512>>>(py);
    head_kernel<<<GG, LAT>>>(fc_w, fc_b, bn_g, bn_b, out);
}

// round 17
// speedup vs baseline: 2.0203x; 1.0787x over previous
#include <cuda_runtime.h>
#include <cuda_fp16.h>
#include <stdint.h>
#include <math.h>

#define NN 50000
#define EE 800000
#define HID 128
#define GG 128
#define LAT 32
#define NEG 0.2f
#define XK 64
#define SCB 196   // ceil(NN/256) scan blocks

// ---------------- scratch (static device memory; zero-initialized) ----------------
__device__ uint32_t g_h[NN * 64];        // gemm output, packed fp16x2
__device__ uint32_t g_y[NN * 64];        // agg output, packed fp16x2
__device__ __half g_w0h[128 * 64],  g_w0l[128 * 64];    // W^T [n][k] fp16 hi/lo
__device__ __half g_w1h[128 * 128], g_w1l[128 * 128];
__device__ __half g_w2h[128 * 128], g_w2l[128 * 128];
__device__ float g_as[NN * 4];
__device__ float g_ad[NN * 4];
__device__ int   g_deg[NN];              // invariant: zero before/after each launch
__device__ int   g_rowoff[NN + 1];
__device__ int   g_cur[NN];
__device__ int   g_csr[EE + NN];
__device__ int   g_goff[GG + 1];
__device__ int   g_bsum[SCB];
__device__ int   g_boff[SCB];
__device__ float g_pool[GG * HID];

// ---------------- prep: split W^T into fp16 hi/lo (tiny) ----------------
__device__ __forceinline__ void hsplit(float v, __half& h, __half& l) {
    h = __float2half(v);
    l = __float2half(v - __half2float(h));
}

__global__ void prepw_kernel(const float* __restrict__ W0, const float* __restrict__ W1,
                             const float* __restrict__ W2)
{
    int i = blockIdx.x * blockDim.x + threadIdx.x;
    if (i < 128 * 64) {
        int n = i / 64, k = i % 64;
        hsplit(W0[k * 128 + n], g_w0h[n * 64 + k], g_w0l[n * 64 + k]);
        return;
    }
    i -= 128 * 64;
    if (i < 128 * 128) {
        int n = i >> 7, k = i & 127;
        hsplit(W1[k * 128 + n], g_w1h[n * 128 + k], g_w1l[n * 128 + k]);
        return;
    }
    i -= 128 * 128;
    if (i < 128 * 128) {
        int n = i >> 7, k = i & 127;
        hsplit(W2[k * 128 + n], g_w2h[n * 128 + k], g_w2l[n * 128 + k]);
    }
}

// ---------------- CSR build ----------------
__global__ void hist_kernel(const int* __restrict__ dst) {
    int i = blockIdx.x * blockDim.x + threadIdx.x;
    if (i < EE) atomicAdd(&g_deg[dst[i]], 1);
}

__global__ void scan1_kernel() {
    __shared__ int red[256];
    int i = blockIdx.x * 256 + threadIdx.x;
    int v = (i < NN) ? (g_deg[i] + 1) : 0;
    red[threadIdx.x] = v;
    __syncthreads();
#pragma unroll
    for (int off = 128; off; off >>= 1) {
        if (threadIdx.x < off) red[threadIdx.x] += red[threadIdx.x + off];
        __syncthreads();
    }
    if (threadIdx.x == 0) g_bsum[blockIdx.x] = red[0];
}

__global__ void scan2_kernel() {
    __shared__ int sc[256];
    int t = threadIdx.x;
    sc[t] = (t < SCB) ? g_bsum[t] : 0;
    __syncthreads();
    for (int off = 1; off < 256; off <<= 1) {
        int v = (t >= off) ? sc[t - off] : 0;
        __syncthreads();
        sc[t] += v;
        __syncthreads();
    }
    if (t < SCB) g_boff[t] = sc[t] - g_bsum[t];
}

__global__ void scan3_kernel() {
    __shared__ int sc[256];
    int t = threadIdx.x;
    int i = blockIdx.x * 256 + t;
    int v = (i < NN) ? (g_deg[i] + 1) : 0;
    sc[t] = v;
    __syncthreads();
    for (int off = 1; off < 256; off <<= 1) {
        int u = (t >= off) ? sc[t - off] : 0;
        __syncthreads();
        sc[t] += u;
        __syncthreads();
    }
    int excl = sc[t] - v + g_boff[blockIdx.x];
    if (i < NN) {
        g_rowoff[i] = excl;
        g_cur[i] = excl;
        g_deg[i] = 0;
        if (i == NN - 1) g_rowoff[NN] = excl + v;
    }
}

__global__ void scatter_kernel(const int* __restrict__ src, const int* __restrict__ dst) {
    int i = blockIdx.x * blockDim.x + threadIdx.x;
    if (i < EE) {
        int d = dst[i];
        int pos = atomicAdd(&g_cur[d], 1);
        g_csr[pos] = src[i];
    } else if (i < EE + NN) {
        int n = i - EE;
        int pos = atomicAdd(&g_cur[n], 1);
        g_csr[pos] = n;
    }
}

__global__ void gbound_kernel(const int* __restrict__ batch) {
    int i = blockIdx.x * blockDim.x + threadIdx.x;
    if (i >= NN) return;
    int b = batch[i];
    int prev = (i == 0) ? -1 : batch[i - 1];
    for (int g = prev + 1; g <= b; g++) g_goff[g] = i;
    if (i == NN - 1) {
        for (int g = b + 1; g <= GG; g++) g_goff[g] = NN;
    }
}

// ---------------- HMMA fp16 GEMM, W split hi/lo (2 MMAs); fused alpha -----------
// D = X*(Wh+Wl), X single fp16 (error random per node -> pools out),
// W error ~2^-22 (negligible). A in fp16, B fp16 hi/lo.
#define ASTR 40

#define MMAF16(d, a, b0v, b1v) \
    asm volatile("mma.sync.aligned.m16n8k16.row.col.f32.f16.f16.f32 " \
        "{%0,%1,%2,%3}, {%4,%5,%6,%7}, {%8,%9}, {%0,%1,%2,%3};" \
        : "+f"((d)[0]), "+f"((d)[1]), "+f"((d)[2]), "+f"((d)[3]) \
        : "r"((a)[0]), "r"((a)[1]), "r"((a)[2]), "r"((a)[3]), "r"(b0v), "r"(b1v))

__global__ __launch_bounds__(256, 2) void gemm_kernel(
    const void* __restrict__ Xv, int xhalf,
    const __half* __restrict__ Bh, const __half* __restrict__ Bl,
    uint32_t* __restrict__ Out, int nrows, int K,
    const float* __restrict__ a_src, const float* __restrict__ a_dst)
{
    __shared__ __align__(16) __half A_s[128 * ASTR];
    __shared__ __align__(16) __half Bh_s[128 * ASTR];
    __shared__ __align__(16) __half Bl_s[128 * ASTR];
    __shared__ float spart[128][4][2];
    __shared__ float sAs[128], sAd[128];

    int tid = threadIdx.x;
    int wid = tid >> 5, lane = tid & 31;
    int g = lane >> 2, tg = lane & 3;
    int rbase = (wid >> 1) * 32;
    int cbase = (wid & 1) * 64;
    int row0 = blockIdx.x * 128;

    if (tid < 128) { sAs[tid] = a_src[tid]; sAd[tid] = a_dst[tid]; }

    float acc[2][8][4];
#pragma unroll
    for (int mt = 0; mt < 2; mt++)
#pragma unroll
        for (int nt = 0; nt < 8; nt++)
#pragma unroll
            for (int q = 0; q < 4; q++) acc[mt][nt][q] = 0.f;

    int lrow = tid >> 1, lhalf = tid & 1;
    int grow = row0 + lrow;
    bool valid = grow < nrows;
    int k0 = lhalf * 16;

    const int NCH = K >> 5;
    for (int ch = 0; ch < NCH; ch++) {
        // A: 16 fp16 channels at k = ch*32 + k0
        if (xhalf) {
            const uint4* xs = (const uint4*)((const __half*)Xv + (size_t)grow * K + ch * 32 + k0);
            uint4 v0 = make_uint4(0, 0, 0, 0), v1 = v0;
            if (valid) { v0 = __ldg(xs); v1 = __ldg(xs + 1); }
            uint4* d = (uint4*)&A_s[lrow * ASTR + k0];
            d[0] = v0; d[1] = v1;
        } else {
            const float4* xs = (const float4*)((const float*)Xv + (size_t)grow * K + ch * 32 + k0);
            uint32_t* d = (uint32_t*)&A_s[lrow * ASTR + k0];
#pragma unroll
            for (int j = 0; j < 4; j++) {
                float4 v = make_float4(0.f, 0.f, 0.f, 0.f);
                if (valid) v = __ldg(xs + j);
                __half2 p0 = __floats2half2_rn(v.x, v.y);
                __half2 p1 = __floats2half2_rn(v.z, v.w);
                d[j * 2]     = *(uint32_t*)&p0;
                d[j * 2 + 1] = *(uint32_t*)&p1;
            }
        }
        // B: pre-split fp16 hi/lo, direct copy
        {
            const uint4* ph = (const uint4*)(Bh + (size_t)lrow * K + ch * 32 + k0);
            const uint4* pl = (const uint4*)(Bl + (size_t)lrow * K + ch * 32 + k0);
            uint4 vh0 = __ldg(ph), vh1 = __ldg(ph + 1);
            uint4 vl0 = __ldg(pl), vl1 = __ldg(pl + 1);
            uint4* dh = (uint4*)&Bh_s[lrow * ASTR + k0];
            uint4* dl = (uint4*)&Bl_s[lrow * ASTR + k0];
            dh[0] = vh0; dh[1] = vh1;
            dl[0] = vl0; dl[1] = vl1;
        }
        __syncthreads();

#pragma unroll
        for (int ks = 0; ks < 2; ks++) {
            int kb = ks * 16;
            uint32_t ah[2][4];
#pragma unroll
            for (int mt = 0; mt < 2; mt++) {
                int r = rbase + mt * 16 + g;
                const __half* ap = &A_s[r * ASTR + kb + tg * 2];
                ah[mt][0] = *(const uint32_t*)ap;
                ah[mt][1] = *(const uint32_t*)(ap + 8 * ASTR);
                ah[mt][2] = *(const uint32_t*)(ap + 8);
                ah[mt][3] = *(const uint32_t*)(ap + 8 * ASTR + 8);
            }
#pragma unroll
            for (int nt = 0; nt < 8; nt++) {
                int nb = cbase + nt * 8 + g;
                const __half* bp = &Bh_s[nb * ASTR + kb + tg * 2];
                uint32_t bh0 = *(const uint32_t*)bp;
                uint32_t bh1 = *(const uint32_t*)(bp + 8);
                const __half* qp = &Bl_s[nb * ASTR + kb + tg * 2];
                uint32_t bl0 = *(const uint32_t*)qp;
                uint32_t bl1 = *(const uint32_t*)(qp + 8);
#pragma unroll
                for (int mt = 0; mt < 2; mt++) {
                    MMAF16(acc[mt][nt], ah[mt], bh0, bh1);
                    MMAF16(acc[mt][nt], ah[mt], bl0, bl1);
                }
            }
        }
        __syncthreads();
    }

    // ---- fused alpha partials (fp32) ----
    {
        float pA[2][2][2], pD[2][2][2];
#pragma unroll
        for (int mt = 0; mt < 2; mt++)
#pragma unroll
            for (int sb = 0; sb < 2; sb++)
#pragma unroll
                for (int hh = 0; hh < 2; hh++) { pA[mt][sb][hh] = 0.f; pD[mt][sb][hh] = 0.f; }
#pragma unroll
        for (int mt = 0; mt < 2; mt++)
#pragma unroll
            for (int nt = 0; nt < 8; nt++) {
                int hh = nt >> 2;
                int c0 = cbase + nt * 8 + tg * 2;
                float a0 = sAs[c0], a1 = sAs[c0 + 1];
                float d0 = sAd[c0], d1 = sAd[c0 + 1];
                pA[mt][0][hh] += acc[mt][nt][0] * a0 + acc[mt][nt][1] * a1;
                pA[mt][1][hh] += acc[mt][nt][2] * a0 + acc[mt][nt][3] * a1;
                pD[mt][0][hh] += acc[mt][nt][0] * d0 + acc[mt][nt][1] * d1;
                pD[mt][1][hh] += acc[mt][nt][2] * d0 + acc[mt][nt][3] * d1;
            }
#pragma unroll
        for (int mt = 0; mt < 2; mt++)
#pragma unroll
            for (int sb = 0; sb < 2; sb++)
#pragma unroll
                for (int hh = 0; hh < 2; hh++) {
                    float vA = pA[mt][sb][hh], vD = pD[mt][sb][hh];
                    vA += __shfl_xor_sync(0xffffffffu, vA, 1);
                    vA += __shfl_xor_sync(0xffffffffu, vA, 2);
                    vD += __shfl_xor_sync(0xffffffffu, vD, 1);
                    vD += __shfl_xor_sync(0xffffffffu, vD, 2);
                    if (tg == 0) {
                        int row = rbase + mt * 16 + sb * 8 + g;
                        int head = (wid & 1) * 2 + hh;
                        spart[row][head][0] = vA;
                        spart[row][head][1] = vD;
                    }
                }
    }

    // ---- store Out as packed fp16x2 ----
#pragma unroll
    for (int mt = 0; mt < 2; mt++) {
        int r1 = row0 + rbase + mt * 16 + g;
        int r2 = r1 + 8;
#pragma unroll
        for (int nt = 0; nt < 8; nt++) {
            int cw = (cbase >> 1) + nt * 4 + tg;
            if (r1 < nrows) {
                __half2 p = __floats2half2_rn(acc[mt][nt][0], acc[mt][nt][1]);
                Out[(size_t)r1 * 64 + cw] = *(uint32_t*)&p;
            }
            if (r2 < nrows) {
                __half2 p = __floats2half2_rn(acc[mt][nt][2], acc[mt][nt][3]);
                Out[(size_t)r2 * 64 + cw] = *(uint32_t*)&p;
            }
        }
    }

    __syncthreads();
    if (tid < 128) {
        int gr = row0 + tid;
        if (gr < nrows) {
            *(float4*)&g_as[gr * 4] = make_float4(spart[tid][0][0], spart[tid][1][0],
                                                  spart[tid][2][0], spart[tid][3][0]);
            *(float4*)&g_ad[gr * 4] = make_float4(spart[tid][0][1], spart[tid][1][1],
                                                  spart[tid][2][1], spart[tid][3][1]);
        }
    }
}

// ---------------- aggregation: one warp per dst node; fp16 in, fp16 out ---------
__global__ __launch_bounds__(256) void agg_kernel(
    const uint32_t* __restrict__ hbuf, const float* __restrict__ bias,
    uint32_t* __restrict__ outbuf)
{
    __shared__ int    s_src[8][32];
    __shared__ float4 s_p[8][32];

    int wi = threadIdx.x >> 5;
    int n = (blockIdx.x * blockDim.x + threadIdx.x) >> 5;
    if (n >= NN) return;
    int lane = threadIdx.x & 31;
    int head = lane >> 3;
    int cw = head * 16 + (lane & 7) * 2;

    float4 adv = *(const float4*)&g_ad[n * 4];
    int beg = g_rowoff[n], end = g_rowoff[n + 1];
    int cntA = end - beg;

    float4 acc = make_float4(0.f, 0.f, 0.f, 0.f);
    float4 acc2 = acc;
    float4 ss  = acc;

    if (cntA <= 32) {
        bool act = lane < cntA;
        int s = 0;
        float4 ev = make_float4(-1e30f, -1e30f, -1e30f, -1e30f);
        if (act) {
            s = __ldg(&g_csr[beg + lane]);
            float4 a = __ldg((const float4*)&g_as[s * 4]);
            float e;
            e = a.x + adv.x; ev.x = fmaxf(e, NEG * e);
            e = a.y + adv.y; ev.y = fmaxf(e, NEG * e);
            e = a.z + adv.z; ev.z = fmaxf(e, NEG * e);
            e = a.w + adv.w; ev.w = fmaxf(e, NEG * e);
        }
        float4 mx = ev;
#pragma unroll
        for (int off = 16; off; off >>= 1) {
            mx.x = fmaxf(mx.x, __shfl_xor_sync(0xffffffffu, mx.x, off));
            mx.y = fmaxf(mx.y, __shfl_xor_sync(0xffffffffu, mx.y, off));
            mx.z = fmaxf(mx.z, __shfl_xor_sync(0xffffffffu, mx.z, off));
            mx.w = fmaxf(mx.w, __shfl_xor_sync(0xffffffffu, mx.w, off));
        }
        float4 pv = make_float4(0.f, 0.f, 0.f, 0.f);
        if (act) {
            pv.x = __expf(ev.x - mx.x);
            pv.y = __expf(ev.y - mx.y);
            pv.z = __expf(ev.z - mx.z);
            pv.w = __expf(ev.w - mx.w);
            ss = pv;
        }
        s_src[wi][lane] = s;
        s_p[wi][lane] = pv;
        __syncwarp();
        int j = 0;
        for (; j + 2 <= cntA; j += 2) {
            int sj0 = s_src[wi][j];
            int sj1 = s_src[wi][j + 1];
            float pj0 = ((const float*)&s_p[wi][j])[head];
            float pj1 = ((const float*)&s_p[wi][j + 1])[head];
            uint2 q0 = __ldg((const uint2*)(hbuf + (size_t)sj0 * 64 + cw));
            uint2 q1 = __ldg((const uint2*)(hbuf + (size_t)sj1 * 64 + cw));
            float2 f0a = __half22float2(*(__half2*)&q0.x);
            float2 f0b = __half22float2(*(__half2*)&q0.y);
            float2 f1a = __half22float2(*(__half2*)&q1.x);
            float2 f1b = __half22float2(*(__half2*)&q1.y);
            acc.x = fmaf(pj0, f0a.x, acc.x);   acc.y = fmaf(pj0, f0a.y, acc.y);
            acc.z = fmaf(pj0, f0b.x, acc.z);   acc.w = fmaf(pj0, f0b.y, acc.w);
            acc2.x = fmaf(pj1, f1a.x, acc2.x); acc2.y = fmaf(pj1, f1a.y, acc2.y);
            acc2.z = fmaf(pj1, f1b.x, acc2.z); acc2.w = fmaf(pj1, f1b.y, acc2.w);
        }
        if (j < cntA) {
            int sj = s_src[wi][j];
            float pj = ((const float*)&s_p[wi][j])[head];
            uint2 q = __ldg((const uint2*)(hbuf + (size_t)sj * 64 + cw));
            float2 fa = __half22float2(*(__half2*)&q.x);
            float2 fb = __half22float2(*(__half2*)&q.y);
            acc.x = fmaf(pj, fa.x, acc.x);
            acc.y = fmaf(pj, fa.y, acc.y);
            acc.z = fmaf(pj, fb.x, acc.z);
            acc.w = fmaf(pj, fb.y, acc.w);
        }
        __syncwarp();
    } else {
        float4 mx = make_float4(-1e30f, -1e30f, -1e30f, -1e30f);
        for (int p = beg + lane; p < end; p += 32) {
            int s = __ldg(&g_csr[p]);
            float4 a = __ldg((const float4*)&g_as[s * 4]);
            float e;
            e = a.x + adv.x; mx.x = fmaxf(mx.x, fmaxf(e, NEG * e));
            e = a.y + adv.y; mx.y = fmaxf(mx.y, fmaxf(e, NEG * e));
            e = a.z + adv.z; mx.z = fmaxf(mx.z, fmaxf(e, NEG * e));
            e = a.w + adv.w; mx.w = fmaxf(mx.w, fmaxf(e, NEG * e));
        }
#pragma unroll
        for (int off = 16; off; off >>= 1) {
            mx.x = fmaxf(mx.x, __shfl_xor_sync(0xffffffffu, mx.x, off));
            mx.y = fmaxf(mx.y, __shfl_xor_sync(0xffffffffu, mx.y, off));
            mx.z = fmaxf(mx.z, __shfl_xor_sync(0xffffffffu, mx.z, off));
            mx.w = fmaxf(mx.w, __shfl_xor_sync(0xffffffffu, mx.w, off));
        }
        for (int p0 = beg; p0 < end; p0 += 32) {
            int cnt = min(32, end - p0);
            float4 pv = make_float4(0.f, 0.f, 0.f, 0.f);
            int s = 0;
            if (lane < cnt) {
                s = __ldg(&g_csr[p0 + lane]);
                float4 a = __ldg((const float4*)&g_as[s * 4]);
                float e;
                e = a.x + adv.x; e = fmaxf(e, NEG * e); pv.x = __expf(e - mx.x);
                e = a.y + adv.y; e = fmaxf(e, NEG * e); pv.y = __expf(e - mx.y);
                e = a.z + adv.z; e = fmaxf(e, NEG * e); pv.z = __expf(e - mx.z);
                e = a.w + adv.w; e = fmaxf(e, NEG * e); pv.w = __expf(e - mx.w);
                ss.x += pv.x; ss.y += pv.y; ss.z += pv.z; ss.w += pv.w;
            }
            s_src[wi][lane] = s;
            s_p[wi][lane] = pv;
            __syncwarp();
            for (int j = 0; j < cnt; j++) {
                int sj = s_src[wi][j];
                float pj = ((const float*)&s_p[wi][j])[head];
                uint2 q = __ldg((const uint2*)(hbuf + (size_t)sj * 64 + cw));
                float2 fa = __half22float2(*(__half2*)&q.x);
                float2 fb = __half22float2(*(__half2*)&q.y);
                acc.x = fmaf(pj, fa.x, acc.x);
                acc.y = fmaf(pj, fa.y, acc.y);
                acc.z = fmaf(pj, fb.x, acc.z);
                acc.w = fmaf(pj, fb.y, acc.w);
            }
            __syncwarp();
        }
    }

    acc.x += acc2.x; acc.y += acc2.y; acc.z += acc2.z; acc.w += acc2.w;

#pragma unroll
    for (int off = 16; off; off >>= 1) {
        ss.x += __shfl_xor_sync(0xffffffffu, ss.x, off);
        ss.y += __shfl_xor_sync(0xffffffffu, ss.y, off);
        ss.z += __shfl_xor_sync(0xffffffffu, ss.z, off);
        ss.w += __shfl_xor_sync(0xffffffffu, ss.w, off);
    }
    float sh = (head == 0) ? ss.x : (head == 1) ? ss.y : (head == 2) ? ss.z : ss.w;
    float inv = 1.0f / (sh + 1e-16f);

    int col = head * 32 + (lane & 7) * 4;
    float4 b = *(const float4*)(bias + col);
    float4 o;
    o.x = acc.x * inv + b.x; o.x = fmaxf(o.x, NEG * o.x);
    o.y = acc.y * inv + b.y; o.y = fmaxf(o.y, NEG * o.y);
    o.z = acc.z * inv + b.z; o.z = fmaxf(o.z, NEG * o.z);
    o.w = acc.w * inv + b.w; o.w = fmaxf(o.w, NEG * o.w);
    __half2 pa = __floats2half2_rn(o.x, o.y);
    __half2 pb = __floats2half2_rn(o.z, o.w);
    *(uint2*)(outbuf + (size_t)n * 64 + cw) = make_uint2(*(uint32_t*)&pa, *(uint32_t*)&pb);
}

// ---------------- pooling: segmented over sorted batch (fp16x2 input) ----------
__global__ __launch_bounds__(512) void pool_kernel() {
    __shared__ float2 sh[8][64];
    int g = blockIdx.x;
    int s = g_goff[g], e = g_goff[g + 1];
    int cword = threadIdx.x & 63;
    int r = threadIdx.x >> 6;     // 0..7
    float2 a = make_float2(0.f, 0.f);
    for (int i = s + r; i < e; i += 8) {
        uint32_t q = __ldg(&g_y[(size_t)i * 64 + cword]);
        float2 f = __half22float2(*(__half2*)&q);
        a.x += f.x; a.y += f.y;
    }
    sh[r][cword] = a;
    __syncthreads();
    if (r == 0) {
        float sx = 0.f, sy = 0.f;
#pragma unroll
        for (int k = 0; k < 8; k++) { sx += sh[k][cword].x; sy += sh[k][cword].y; }
        g_pool[g * 128 + cword * 2]     = sx;
        g_pool[g * 128 + cword * 2 + 1] = sy;
    }
}

// ---------------- head ----------------
__global__ void head_kernel(const float* __restrict__ fc_w, const float* __restrict__ fc_b,
                            const float* __restrict__ bn_g, const float* __restrict__ bn_b,
                            float* __restrict__ out)
{
    int g = blockIdx.x;
    int l = threadIdx.x;
    const float* pr = g_pool + g * HID;
    float s = 0.f;
#pragma unroll 8
    for (int k = 0; k < HID; k++) s = fmaf(pr[k], fc_w[k * LAT + l], s);
    s += fc_b[l];
    const float inv = 0.999995000037499688f;  // 1/sqrt(1 + 1e-5)
    out[g * LAT + l] = bn_g[l] * s * inv + bn_b[l];
}

// ---------------- launch ----------------
extern "C" void kernel_launch(void* const* d_in, const int* in_sizes, int n_in,
                              void* d_out, int out_size)
{
    const float* x       = (const float*)d_in[0];
    const int*   eidx    = (const int*)  d_in[1];
    const int*   batch   = (const int*)  d_in[2];
    const float* W0      = (const float*)d_in[3];
    const float* a_src0  = (const float*)d_in[4];
    const float* a_dst0  = (const float*)d_in[5];
    const float* b0      = (const float*)d_in[6];
    const float* W1      = (const float*)d_in[7];
    const float* a_src1  = (const float*)d_in[8];
    const float* a_dst1  = (const float*)d_in[9];
    const float* b1      = (const float*)d_in[10];
    const float* W2      = (const float*)d_in[11];
    const float* a_src2  = (const float*)d_in[12];
    const float* a_dst2  = (const float*)d_in[13];
    const float* b2      = (const float*)d_in[14];
    const float* fc_w    = (const float*)d_in[15];
    const float* fc_b    = (const float*)d_in[16];
    const float* bn_g    = (const float*)d_in[17];
    const float* bn_b    = (const float*)d_in[18];
    float* out = (float*)d_out;

    const int* src = eidx;
    const int* dst = eidx + EE;

    uint32_t *ph, *py;
    __half *pw0h, *pw0l, *pw1h, *pw1l, *pw2h, *pw2l;
    cudaGetSymbolAddress((void**)&ph, g_h);
    cudaGetSymbolAddress((void**)&py, g_y);
    cudaGetSymbolAddress((void**)&pw0h, g_w0h);
    cudaGetSymbolAddress((void**)&pw0l, g_w0l);
    cudaGetSymbolAddress((void**)&pw1h, g_w1h);
    cudaGetSymbolAddress((void**)&pw1l, g_w1l);
    cudaGetSymbolAddress((void**)&pw2h, g_w2h);
    cudaGetSymbolAddress((void**)&pw2l, g_w2l);

    static cudaStream_t s_side = nullptr;
    static cudaEvent_t s_fork = nullptr, s_join = nullptr;
    if (s_side == nullptr) {
        cudaStreamCreateWithFlags(&s_side, cudaStreamNonBlocking);
        cudaEventCreateWithFlags(&s_fork, cudaEventDisableTiming);
        cudaEventCreateWithFlags(&s_join, cudaEventDisableTiming);
    }

    const int PREPW_TOT = 128 * 64 + 2 * 128 * 128;
    const int gemm_grid = (NN + 127) / 128;
    const int warp_grid = (NN + 7) / 8;

    cudaEventRecord(s_fork, 0);
    cudaStreamWaitEvent(s_side, s_fork, 0);

    hist_kernel<<<(EE + 255) / 256, 256, 0, s_side>>>(dst);
    scan1_kernel<<<SCB, 256, 0, s_side>>>();
    scan2_kernel<<<1, 256, 0, s_side>>>();
    scan3_kernel<<<SCB, 256, 0, s_side>>>();
    scatter_kernel<<<(EE + NN + 255) / 256, 256, 0, s_side>>>(src, dst);
    gbound_kernel<<<(NN + 255) / 256, 256, 0, s_side>>>(batch);
    cudaEventRecord(s_join, s_side);

    prepw_kernel<<<(PREPW_TOT + 255) / 256, 256>>>(W0, W1, W2);
    gemm_kernel<<<gemm_grid, 256>>>(x, 0, pw0h, pw0l, ph, NN, XK, a_src0, a_dst0);

    cudaStreamWaitEvent(0, s_join, 0);
    agg_kernel<<<warp_grid, 256>>>(ph, b0, py);

    gemm_kernel<<<gemm_grid, 256>>>(py, 1, pw1h, pw1l, ph, NN, HID, a_src1, a_dst1);
    agg_kernel<<<warp_grid, 256>>>(ph, b1, py);

    gemm_kernel<<<gemm_grid, 256>>>(py, 1, pw2h, pw2l, ph, NN, HID, a_src2, a_dst2);
    agg_kernel<<<warp_grid, 256>>>(ph, b2, py);

    pool_kernel<<<GG, 512>>>();
    head_kernel<<<GG, LAT>>>(fc_w, fc_b, bn_g, bn_b, out);
}